// round 4
// baseline (speedup 1.0000x reference)
#include <cuda_runtime.h>
#include <cuda_fp16.h>
#include <stdint.h>

#define N_NODES 100000
#define F_IN    512
#define HID     64
#define NCLS    64
#define BM      128
#define KCH     32
#define NCHUNK  (F_IN / KCH)   // 16

// fp16 logits scratch (halves scatter gather traffic). 12.8 MB.
__device__ __align__(16) __half g_logits_h[(size_t)N_NODES * NCLS];

__device__ __forceinline__ uint32_t f2tf32(float f) {
    uint32_t o; asm("cvt.rna.tf32.f32 %0, %1;" : "=r"(o) : "f"(f)); return o;
}
__device__ __forceinline__ void mma_tf32(float* c, const uint32_t* a, const uint32_t* b) {
    asm volatile("mma.sync.aligned.m16n8k8.row.col.f32.tf32.tf32.f32 "
        "{%0,%1,%2,%3}, {%4,%5,%6,%7}, {%8,%9}, {%0,%1,%2,%3};\n"
        : "+f"(c[0]), "+f"(c[1]), "+f"(c[2]), "+f"(c[3])
        : "r"(a[0]), "r"(a[1]), "r"(a[2]), "r"(a[3]), "r"(b[0]), "r"(b[1]));
}
__device__ __forceinline__ void mma_f16(float* c, const uint32_t* a, const uint32_t* b) {
    asm volatile("mma.sync.aligned.m16n8k16.row.col.f32.f16.f16.f32 "
        "{%0,%1,%2,%3}, {%4,%5,%6,%7}, {%8,%9}, {%0,%1,%2,%3};\n"
        : "+f"(c[0]), "+f"(c[1]), "+f"(c[2]), "+f"(c[3])
        : "r"(a[0]), "r"(a[1]), "r"(a[2]), "r"(a[3]), "r"(b[0]), "r"(b[1]));
}

// ---------------------------------------------------------------------------
// Fused MLP on tensor cores with software-pipelined GEMM1.
//   h = relu(X @ W1 + b1)  -> tf32 mma, fp32 accum
//   logits = h @ W2 + b2   -> f16 mma, fp32 accum, stored fp16
// Block: 128 rows, 8 warps in a 4(M) x 2(N) grid; warp tile 32x32.
// ---------------------------------------------------------------------------
__global__ __launch_bounds__(256) void mlp_mma(
    const float* __restrict__ X,
    const float* __restrict__ W1,
    const float* __restrict__ b1,
    const float* __restrict__ W2,
    const float* __restrict__ b2)
{
    // Double-buffered tf32 tiles; phase-2 arrays overlay buffer 0 regions.
    // Xs: 2 x [128][36] (4608 words each). Ws: 2 x [32][72] (2304 words each).
    __shared__ __align__(16) uint32_t smem[2 * 4608 + 2 * 2304];
    uint32_t* XsBase = smem;            // +b*4608
    uint32_t* WsBase = smem + 9216;     // +b*2304
    uint32_t (*H2)[36]  = (uint32_t(*)[36])smem;           // half2 [128][36]
    uint32_t (*W2p)[72] = (uint32_t(*)[72])(smem + 9216);  // half2 [32][72]

    const int t    = threadIdx.x;
    const int lane = t & 31;
    const int wid  = t >> 5;
    const int wm   = wid & 3;     // warp M index (rows 32*wm)
    const int wn   = wid >> 2;    // warp N index (cols 32*wn)
    const int g    = lane >> 2;   // 0..7
    const int tq   = lane & 3;    // 0..3
    const int rb   = blockIdx.x * BM;

    // Per-thread tile-load geometry (constant across chunks)
    const int xrow[4] = { (t) >> 3, (t + 256) >> 3, (t + 512) >> 3, (t + 768) >> 3 };
    const int xc4     = (t & 7) * 4;
    const int wkr[2]  = { t >> 4, (t + 256) >> 4 };
    const int wc4     = (t & 15) * 4;

    float4 xr[4], wr[2];

    auto load_tiles = [&](int cc) {
        const int kb = cc * KCH;
#pragma unroll
        for (int l = 0; l < 4; l++) {
            int grow = rb + xrow[l];
            xr[l] = (grow < N_NODES)
                  ? *(const float4*)(X + (size_t)grow * F_IN + kb + xc4)
                  : make_float4(0.f, 0.f, 0.f, 0.f);
        }
#pragma unroll
        for (int l = 0; l < 2; l++)
            wr[l] = *(const float4*)(W1 + (size_t)(kb + wkr[l]) * HID + wc4);
    };
    auto store_tiles = [&](int b) {
        uint32_t* Xs = XsBase + b * 4608;
        uint32_t* Ws = WsBase + b * 2304;
#pragma unroll
        for (int l = 0; l < 4; l++) {
            uint4 u;
            u.x = f2tf32(xr[l].x); u.y = f2tf32(xr[l].y);
            u.z = f2tf32(xr[l].z); u.w = f2tf32(xr[l].w);
            *(uint4*)(Xs + xrow[l] * 36 + xc4) = u;
        }
#pragma unroll
        for (int l = 0; l < 2; l++) {
            uint4 u;
            u.x = f2tf32(wr[l].x); u.y = f2tf32(wr[l].y);
            u.z = f2tf32(wr[l].z); u.w = f2tf32(wr[l].w);
            *(uint4*)(Ws + wkr[l] * 72 + wc4) = u;
        }
    };

    float c1[2][4][4];
#pragma unroll
    for (int m = 0; m < 2; m++)
#pragma unroll
        for (int n = 0; n < 4; n++)
#pragma unroll
            for (int i = 0; i < 4; i++) c1[m][n][i] = 0.0f;

    load_tiles(0);
    store_tiles(0);
    __syncthreads();

#pragma unroll 1
    for (int cc = 0; cc < NCHUNK; cc++) {
        if (cc + 1 < NCHUNK) load_tiles(cc + 1);   // prefetch into regs

        const uint32_t* Xs = XsBase + (cc & 1) * 4608;
        const uint32_t* Ws = WsBase + (cc & 1) * 2304;
#pragma unroll
        for (int ka = 0; ka < 4; ka++) {
            const int k0 = ka * 8;
            uint32_t a[2][4];
#pragma unroll
            for (int m = 0; m < 2; m++) {
                int row = wm * 32 + m * 16;
                a[m][0] = Xs[(row + g    ) * 36 + k0 + tq];
                a[m][1] = Xs[(row + g + 8) * 36 + k0 + tq];
                a[m][2] = Xs[(row + g    ) * 36 + k0 + tq + 4];
                a[m][3] = Xs[(row + g + 8) * 36 + k0 + tq + 4];
            }
            uint32_t b[4][2];
#pragma unroll
            for (int n = 0; n < 4; n++) {
                int col = wn * 32 + n * 8 + g;
                b[n][0] = Ws[(k0 + tq    ) * 72 + col];
                b[n][1] = Ws[(k0 + tq + 4) * 72 + col];
            }
#pragma unroll
            for (int m = 0; m < 2; m++)
#pragma unroll
                for (int n = 0; n < 4; n++)
                    mma_tf32(c1[m][n], a[m], b[n]);
        }

        if (cc + 1 < NCHUNK) store_tiles((cc + 1) & 1);  // other buffer: no race
        __syncthreads();
    }

    // bias + relu -> fp16 pairs into H2 (overlays Xs buf0; all mma reads done)
#pragma unroll
    for (int n = 0; n < 4; n++) {
        float2 bb = *(const float2*)(b1 + wn * 32 + n * 8 + 2 * tq);
        int colp = wn * 16 + n * 4 + tq;
#pragma unroll
        for (int m = 0; m < 2; m++) {
            int row = wm * 32 + m * 16 + g;
            float h0 = fmaxf(c1[m][n][0] + bb.x, 0.f);
            float h1 = fmaxf(c1[m][n][1] + bb.y, 0.f);
            float h2 = fmaxf(c1[m][n][2] + bb.x, 0.f);
            float h3 = fmaxf(c1[m][n][3] + bb.y, 0.f);
            __half2 p0 = __floats2half2_rn(h0, h1);
            __half2 p1 = __floats2half2_rn(h2, h3);
            H2[row    ][colp] = *(uint32_t*)&p0;
            H2[row + 8][colp] = *(uint32_t*)&p1;
        }
    }
    // W2 -> fp16 k-pair layout: W2p[k/2][n] = {W2[k][n], W2[k+1][n]}
#pragma unroll
    for (int l = 0; l < 8; l++) {
        int idx = t + l * 256;          // 0..2047
        int kp  = idx >> 6;             // 0..31
        int n   = idx & 63;
        float w0 = W2[(size_t)(2 * kp    ) * NCLS + n];
        float w1 = W2[(size_t)(2 * kp + 1) * NCLS + n];
        __half2 p = __floats2half2_rn(w0, w1);
        W2p[kp][n] = *(uint32_t*)&p;
    }
    __syncthreads();

    float c2[2][4][4];
#pragma unroll
    for (int m = 0; m < 2; m++)
#pragma unroll
        for (int n = 0; n < 4; n++)
#pragma unroll
            for (int i = 0; i < 4; i++) c2[m][n][i] = 0.0f;

#pragma unroll
    for (int ka = 0; ka < 4; ka++) {
        const int kp = ka * 8;          // half2-pair base (covers k = 16*ka .. +15)
        uint32_t a[2][4];
#pragma unroll
        for (int m = 0; m < 2; m++) {
            int row = wm * 32 + m * 16;
            a[m][0] = H2[row + g    ][kp + tq];
            a[m][1] = H2[row + g + 8][kp + tq];
            a[m][2] = H2[row + g    ][kp + tq + 4];
            a[m][3] = H2[row + g + 8][kp + tq + 4];
        }
        uint32_t b[4][2];
#pragma unroll
        for (int n = 0; n < 4; n++) {
            int col = wn * 32 + n * 8 + g;
            b[n][0] = W2p[kp + tq    ][col];
            b[n][1] = W2p[kp + tq + 4][col];
        }
#pragma unroll
        for (int m = 0; m < 2; m++)
#pragma unroll
            for (int n = 0; n < 4; n++)
                mma_f16(c2[m][n], a[m], b[n]);
    }

    // + b2, store logits as fp16
    __half2* lg2 = (__half2*)g_logits_h;
#pragma unroll
    for (int n = 0; n < 4; n++) {
        float2 bb = *(const float2*)(b2 + wn * 32 + n * 8 + 2 * tq);
        int colp = wn * 16 + n * 4 + tq;
#pragma unroll
        for (int m = 0; m < 2; m++) {
            int row = rb + wm * 32 + m * 16 + g;
            if (row < N_NODES)
                lg2[(size_t)row * 32 + colp] =
                    __floats2half2_rn(c2[m][n][0] + bb.x, c2[m][n][1] + bb.y);
            if (row + 8 < N_NODES)
                lg2[(size_t)(row + 8) * 32 + colp] =
                    __floats2half2_rn(c2[m][n][2] + bb.x, c2[m][n][3] + bb.y);
        }
    }
}

// ---------------------------------------------------------------------------
// Edge scatter: out[row] += val * logits[col]
// 16 lanes/edge: 8B fp16 gather per lane (128B/edge contiguous) +
// one contiguous red.v4 per lane (256B/edge contiguous).
// ---------------------------------------------------------------------------
__global__ __launch_bounds__(256) void edge_scatter(
    const int*   __restrict__ rows,
    const int*   __restrict__ cols,
    const float* __restrict__ vals,
    float*       __restrict__ out,
    int E)
{
    long long tid = (long long)blockIdx.x * 256 + threadIdx.x;
    int e = (int)(tid >> 4);
    if (e >= E) return;
    int j = (int)(tid & 15);

    int   r = __ldg(rows + e);
    int   c = __ldg(cols + e);
    float v = __ldg(vals + e);

    uint2 raw = *(const uint2*)(g_logits_h + (size_t)c * NCLS + j * 4);
    float2 f0 = __half22float2(*(const __half2*)&raw.x);
    float2 f1 = __half22float2(*(const __half2*)&raw.y);

    float* dst = out + (size_t)r * NCLS + j * 4;
    asm volatile("red.global.add.v4.f32 [%0], {%1, %2, %3, %4};"
                 :: "l"(dst), "f"(f0.x * v), "f"(f0.y * v), "f"(f1.x * v), "f"(f1.y * v)
                 : "memory");
}

// ---------------------------------------------------------------------------
extern "C" void kernel_launch(void* const* d_in, const int* in_sizes, int n_in,
                              void* d_out, int out_size)
{
    const float* X    = (const float*)d_in[0];
    const int*   erow = (const int*)  d_in[1];
    const int*   ecol = (const int*)  d_in[2];
    const float* ev   = (const float*)d_in[3];
    const float* W1   = (const float*)d_in[4];
    const float* b1   = (const float*)d_in[5];
    const float* W2   = (const float*)d_in[6];
    const float* b2   = (const float*)d_in[7];
    float* out = (float*)d_out;
    int E = in_sizes[1];

    cudaMemsetAsync(d_out, 0, (size_t)out_size * sizeof(float));

    mlp_mma<<<(N_NODES + BM - 1) / BM, 256>>>(X, W1, b1, W2, b2);

    long long threads = (long long)E * 16;
    int blocks = (int)((threads + 255) / 256);
    edge_scatter<<<blocks, 256>>>(erow, ecol, ev, out, E);
}

// round 6
// speedup vs baseline: 1.3648x; 1.3648x over previous
#include <cuda_runtime.h>
#include <cuda_fp16.h>
#include <stdint.h>

#define N_NODES 100000
#define F_IN    512
#define HID     64
#define NCLS    64
#define BM      128
#define KCH     32
#define NCHUNK  (F_IN / KCH)   // 16

// fp32 logits scratch [N_NODES, 64] = 25.6 MB (L2-resident on 126MB L2).
__device__ __align__(16) float g_logits[(size_t)N_NODES * NCLS];

__device__ __forceinline__ uint32_t f2tf32(float f) {
    uint32_t o; asm("cvt.rna.tf32.f32 %0, %1;" : "=r"(o) : "f"(f)); return o;
}
__device__ __forceinline__ void mma_tf32(float* c, const uint32_t* a, const uint32_t* b) {
    asm volatile("mma.sync.aligned.m16n8k8.row.col.f32.tf32.tf32.f32 "
        "{%0,%1,%2,%3}, {%4,%5,%6,%7}, {%8,%9}, {%0,%1,%2,%3};\n"
        : "+f"(c[0]), "+f"(c[1]), "+f"(c[2]), "+f"(c[3])
        : "r"(a[0]), "r"(a[1]), "r"(a[2]), "r"(a[3]), "r"(b[0]), "r"(b[1]));
}
__device__ __forceinline__ void mma_f16(float* c, const uint32_t* a, const uint32_t* b) {
    asm volatile("mma.sync.aligned.m16n8k16.row.col.f32.f16.f16.f32 "
        "{%0,%1,%2,%3}, {%4,%5,%6,%7}, {%8,%9}, {%0,%1,%2,%3};\n"
        : "+f"(c[0]), "+f"(c[1]), "+f"(c[2]), "+f"(c[3])
        : "r"(a[0]), "r"(a[1]), "r"(a[2]), "r"(a[3]), "r"(b[0]), "r"(b[1]));
}

// ---------------------------------------------------------------------------
// Fused MLP on tensor cores with software-pipelined GEMM1.
//   h = relu(X @ W1 + b1)  -> tf32 mma, fp32 accum
//   logits = h @ W2 + b2   -> f16 mma, fp32 accum, stored fp32
// Block: 128 rows, 8 warps in a 4(M) x 2(N) grid; warp tile 32x32.
// ---------------------------------------------------------------------------
__global__ __launch_bounds__(256) void mlp_mma(
    const float* __restrict__ X,
    const float* __restrict__ W1,
    const float* __restrict__ b1,
    const float* __restrict__ W2,
    const float* __restrict__ b2)
{
    // Double-buffered tf32 tiles; phase-2 arrays overlay buffer regions.
    __shared__ __align__(16) uint32_t smem[2 * 4608 + 2 * 2304];
    uint32_t* XsBase = smem;            // +b*4608, [128][36]
    uint32_t* WsBase = smem + 9216;     // +b*2304, [32][72]
    uint32_t (*H2)[36]  = (uint32_t(*)[36])smem;           // half2 [128][36]
    uint32_t (*W2p)[72] = (uint32_t(*)[72])(smem + 9216);  // half2 [32][72]

    const int t    = threadIdx.x;
    const int lane = t & 31;
    const int wid  = t >> 5;
    const int wm   = wid & 3;
    const int wn   = wid >> 2;
    const int g    = lane >> 2;
    const int tq   = lane & 3;
    const int rb   = blockIdx.x * BM;

    const int xrow[4] = { (t) >> 3, (t + 256) >> 3, (t + 512) >> 3, (t + 768) >> 3 };
    const int xc4     = (t & 7) * 4;
    const int wkr[2]  = { t >> 4, (t + 256) >> 4 };
    const int wc4     = (t & 15) * 4;

    float4 xr[4], wr[2];

    auto load_tiles = [&](int cc) {
        const int kb = cc * KCH;
#pragma unroll
        for (int l = 0; l < 4; l++) {
            int grow = rb + xrow[l];
            xr[l] = (grow < N_NODES)
                  ? *(const float4*)(X + (size_t)grow * F_IN + kb + xc4)
                  : make_float4(0.f, 0.f, 0.f, 0.f);
        }
#pragma unroll
        for (int l = 0; l < 2; l++)
            wr[l] = *(const float4*)(W1 + (size_t)(kb + wkr[l]) * HID + wc4);
    };
    auto store_tiles = [&](int b) {
        uint32_t* Xs = XsBase + b * 4608;
        uint32_t* Ws = WsBase + b * 2304;
#pragma unroll
        for (int l = 0; l < 4; l++) {
            uint4 u;
            u.x = f2tf32(xr[l].x); u.y = f2tf32(xr[l].y);
            u.z = f2tf32(xr[l].z); u.w = f2tf32(xr[l].w);
            *(uint4*)(Xs + xrow[l] * 36 + xc4) = u;
        }
#pragma unroll
        for (int l = 0; l < 2; l++) {
            uint4 u;
            u.x = f2tf32(wr[l].x); u.y = f2tf32(wr[l].y);
            u.z = f2tf32(wr[l].z); u.w = f2tf32(wr[l].w);
            *(uint4*)(Ws + wkr[l] * 72 + wc4) = u;
        }
    };

    float c1[2][4][4];
#pragma unroll
    for (int m = 0; m < 2; m++)
#pragma unroll
        for (int n = 0; n < 4; n++)
#pragma unroll
            for (int i = 0; i < 4; i++) c1[m][n][i] = 0.0f;

    load_tiles(0);
    store_tiles(0);
    __syncthreads();

#pragma unroll 1
    for (int cc = 0; cc < NCHUNK; cc++) {
        if (cc + 1 < NCHUNK) load_tiles(cc + 1);

        const uint32_t* Xs = XsBase + (cc & 1) * 4608;
        const uint32_t* Ws = WsBase + (cc & 1) * 2304;
#pragma unroll
        for (int ka = 0; ka < 4; ka++) {
            const int k0 = ka * 8;
            uint32_t a[2][4];
#pragma unroll
            for (int m = 0; m < 2; m++) {
                int row = wm * 32 + m * 16;
                a[m][0] = Xs[(row + g    ) * 36 + k0 + tq];
                a[m][1] = Xs[(row + g + 8) * 36 + k0 + tq];
                a[m][2] = Xs[(row + g    ) * 36 + k0 + tq + 4];
                a[m][3] = Xs[(row + g + 8) * 36 + k0 + tq + 4];
            }
            uint32_t b[4][2];
#pragma unroll
            for (int n = 0; n < 4; n++) {
                int col = wn * 32 + n * 8 + g;
                b[n][0] = Ws[(k0 + tq    ) * 72 + col];
                b[n][1] = Ws[(k0 + tq + 4) * 72 + col];
            }
#pragma unroll
            for (int m = 0; m < 2; m++)
#pragma unroll
                for (int n = 0; n < 4; n++)
                    mma_tf32(c1[m][n], a[m], b[n]);
        }

        if (cc + 1 < NCHUNK) store_tiles((cc + 1) & 1);
        __syncthreads();
    }

    // bias + relu -> fp16 pairs into H2 (overlays Xs; all mma reads done)
#pragma unroll
    for (int n = 0; n < 4; n++) {
        float2 bb = *(const float2*)(b1 + wn * 32 + n * 8 + 2 * tq);
        int colp = wn * 16 + n * 4 + tq;
#pragma unroll
        for (int m = 0; m < 2; m++) {
            int row = wm * 32 + m * 16 + g;
            float h0 = fmaxf(c1[m][n][0] + bb.x, 0.f);
            float h1 = fmaxf(c1[m][n][1] + bb.y, 0.f);
            float h2 = fmaxf(c1[m][n][2] + bb.x, 0.f);
            float h3 = fmaxf(c1[m][n][3] + bb.y, 0.f);
            __half2 p0 = __floats2half2_rn(h0, h1);
            __half2 p1 = __floats2half2_rn(h2, h3);
            H2[row    ][colp] = *(uint32_t*)&p0;
            H2[row + 8][colp] = *(uint32_t*)&p1;
        }
    }
    // W2 -> fp16 k-pair layout: W2p[k/2][n] = {W2[k][n], W2[k+1][n]}
#pragma unroll
    for (int l = 0; l < 8; l++) {
        int idx = t + l * 256;
        int kp  = idx >> 6;
        int n   = idx & 63;
        float w0 = W2[(size_t)(2 * kp    ) * NCLS + n];
        float w1 = W2[(size_t)(2 * kp + 1) * NCLS + n];
        __half2 p = __floats2half2_rn(w0, w1);
        W2p[kp][n] = *(uint32_t*)&p;
    }
    __syncthreads();

    float c2[2][4][4];
#pragma unroll
    for (int m = 0; m < 2; m++)
#pragma unroll
        for (int n = 0; n < 4; n++)
#pragma unroll
            for (int i = 0; i < 4; i++) c2[m][n][i] = 0.0f;

#pragma unroll
    for (int ka = 0; ka < 4; ka++) {
        const int kp = ka * 8;
        uint32_t a[2][4];
#pragma unroll
        for (int m = 0; m < 2; m++) {
            int row = wm * 32 + m * 16;
            a[m][0] = H2[row + g    ][kp + tq];
            a[m][1] = H2[row + g + 8][kp + tq];
            a[m][2] = H2[row + g    ][kp + tq + 4];
            a[m][3] = H2[row + g + 8][kp + tq + 4];
        }
        uint32_t b[4][2];
#pragma unroll
        for (int n = 0; n < 4; n++) {
            int col = wn * 32 + n * 8 + g;
            b[n][0] = W2p[kp + tq    ][col];
            b[n][1] = W2p[kp + tq + 4][col];
        }
#pragma unroll
        for (int m = 0; m < 2; m++)
#pragma unroll
            for (int n = 0; n < 4; n++)
                mma_f16(c2[m][n], a[m], b[n]);
    }

    // + b2, store logits as fp32 (float2 per lane)
    float2* lg = (float2*)g_logits;
#pragma unroll
    for (int n = 0; n < 4; n++) {
        float2 bb = *(const float2*)(b2 + wn * 32 + n * 8 + 2 * tq);
        int colp = wn * 16 + n * 4 + tq;   // float2 index within row (0..31)
#pragma unroll
        for (int m = 0; m < 2; m++) {
            int row = rb + wm * 32 + m * 16 + g;
            if (row < N_NODES) {
                float2 o; o.x = c2[m][n][0] + bb.x; o.y = c2[m][n][1] + bb.y;
                lg[(size_t)row * 32 + colp] = o;
            }
            if (row + 8 < N_NODES) {
                float2 o; o.x = c2[m][n][2] + bb.x; o.y = c2[m][n][3] + bb.y;
                lg[(size_t)(row + 8) * 32 + colp] = o;
            }
        }
    }
}

// ---------------------------------------------------------------------------
// Edge scatter: out[row] += val * logits[col]
// 16 lanes/edge. Leader lane (j==0) loads indices; shfl-broadcast across the
// half-warp. fp32 float4 gather (no converts) + one contiguous red.v4/lane.
// ---------------------------------------------------------------------------
__global__ __launch_bounds__(256) void edge_scatter(
    const int*   __restrict__ rows,
    const int*   __restrict__ cols,
    const float* __restrict__ vals,
    float*       __restrict__ out,
    int E)
{
    long long tid = (long long)blockIdx.x * 256 + threadIdx.x;
    int e = (int)(tid >> 4);
    if (e >= E) return;
    int j = (int)(tid & 15);

    int r = 0, c = 0;
    float v = 0.0f;
    if (j == 0) {
        r = __ldg(rows + e);
        c = __ldg(cols + e);
        v = __ldg(vals + e);
    }
    r = __shfl_sync(0xffffffffu, r, 0, 16);
    c = __shfl_sync(0xffffffffu, c, 0, 16);
    v = __shfl_sync(0xffffffffu, v, 0, 16);

    float4 m = *(const float4*)(g_logits + (size_t)c * NCLS + j * 4);

    float* dst = out + (size_t)r * NCLS + j * 4;
    asm volatile("red.global.add.v4.f32 [%0], {%1, %2, %3, %4};"
                 :: "l"(dst), "f"(m.x * v), "f"(m.y * v), "f"(m.z * v), "f"(m.w * v)
                 : "memory");
}

// ---------------------------------------------------------------------------
extern "C" void kernel_launch(void* const* d_in, const int* in_sizes, int n_in,
                              void* d_out, int out_size)
{
    const float* X    = (const float*)d_in[0];
    const int*   erow = (const int*)  d_in[1];
    const int*   ecol = (const int*)  d_in[2];
    const float* ev   = (const float*)d_in[3];
    const float* W1   = (const float*)d_in[4];
    const float* b1   = (const float*)d_in[5];
    const float* W2   = (const float*)d_in[6];
    const float* b2   = (const float*)d_in[7];
    float* out = (float*)d_out;
    int E = in_sizes[1];

    cudaMemsetAsync(d_out, 0, (size_t)out_size * sizeof(float));

    mlp_mma<<<(N_NODES + BM - 1) / BM, 256>>>(X, W1, b1, W2, b2);

    long long threads = (long long)E * 16;
    int blocks = (int)((threads + 255) / 256);
    edge_scatter<<<blocks, 256>>>(erow, ecol, ev, out, E);
}

// round 9
// speedup vs baseline: 1.7533x; 1.2847x over previous
#include <cuda_runtime.h>
#include <cuda_fp16.h>
#include <stdint.h>

#define N_NODES 100000
#define F_IN    512
#define HID     64
#define NCLS    64
#define BM      128
#define KCH     32
#define NCHUNK  (F_IN / KCH)   // 16
#define MAX_E   3200000
#define SCAN_NB ((N_NODES + 1023) / 1024)   // 98

// fp16 logits scratch [N_NODES, 64] = 12.8 MB.
__device__ __align__(256) __half g_logits_h[(size_t)N_NODES * NCLS];
// CSR machinery
__device__ int  g_cnt[N_NODES];        // per-row counts
__device__ int  g_off[N_NODES];       // exclusive prefix
__device__ int  g_run[N_NODES];       // running cursors for build
__device__ int  g_bsum[SCAN_NB];       // block sums for scan
__device__ __align__(16) int2 g_epack[MAX_E];   // (col, val bits) sorted by row

__device__ __forceinline__ uint32_t f2tf32(float f) {
    uint32_t o; asm("cvt.rna.tf32.f32 %0, %1;" : "=r"(o) : "f"(f)); return o;
}
__device__ __forceinline__ void mma_tf32(float* c, const uint32_t* a, const uint32_t* b) {
    asm volatile("mma.sync.aligned.m16n8k8.row.col.f32.tf32.tf32.f32 "
        "{%0,%1,%2,%3}, {%4,%5,%6,%7}, {%8,%9}, {%0,%1,%2,%3};\n"
        : "+f"(c[0]), "+f"(c[1]), "+f"(c[2]), "+f"(c[3])
        : "r"(a[0]), "r"(a[1]), "r"(a[2]), "r"(a[3]), "r"(b[0]), "r"(b[1]));
}
__device__ __forceinline__ void mma_f16(float* c, const uint32_t* a, const uint32_t* b) {
    asm volatile("mma.sync.aligned.m16n8k16.row.col.f32.f16.f16.f32 "
        "{%0,%1,%2,%3}, {%4,%5,%6,%7}, {%8,%9}, {%0,%1,%2,%3};\n"
        : "+f"(c[0]), "+f"(c[1]), "+f"(c[2]), "+f"(c[3])
        : "r"(a[0]), "r"(a[1]), "r"(a[2]), "r"(a[3]), "r"(b[0]), "r"(b[1]));
}

// ---------------------------------------------------------------------------
// Fused MLP (unchanged pipeline from R6, epilogue stores fp16 logits)
// ---------------------------------------------------------------------------
__global__ __launch_bounds__(256) void mlp_mma(
    const float* __restrict__ X,
    const float* __restrict__ W1,
    const float* __restrict__ b1,
    const float* __restrict__ W2,
    const float* __restrict__ b2)
{
    __shared__ __align__(16) uint32_t smem[2 * 4608 + 2 * 2304];
    uint32_t* XsBase = smem;            // +b*4608, [128][36]
    uint32_t* WsBase = smem + 9216;     // +b*2304, [32][72]
    uint32_t (*H2)[36]  = (uint32_t(*)[36])smem;
    uint32_t (*W2p)[72] = (uint32_t(*)[72])(smem + 9216);

    const int t    = threadIdx.x;
    const int lane = t & 31;
    const int wid  = t >> 5;
    const int wm   = wid & 3;
    const int wn   = wid >> 2;
    const int g    = lane >> 2;
    const int tq   = lane & 3;
    const int rb   = blockIdx.x * BM;

    const int xrow[4] = { (t) >> 3, (t + 256) >> 3, (t + 512) >> 3, (t + 768) >> 3 };
    const int xc4     = (t & 7) * 4;
    const int wkr[2]  = { t >> 4, (t + 256) >> 4 };
    const int wc4     = (t & 15) * 4;

    float4 xr[4], wr[2];

    auto load_tiles = [&](int cc) {
        const int kb = cc * KCH;
#pragma unroll
        for (int l = 0; l < 4; l++) {
            int grow = rb + xrow[l];
            xr[l] = (grow < N_NODES)
                  ? *(const float4*)(X + (size_t)grow * F_IN + kb + xc4)
                  : make_float4(0.f, 0.f, 0.f, 0.f);
        }
#pragma unroll
        for (int l = 0; l < 2; l++)
            wr[l] = *(const float4*)(W1 + (size_t)(kb + wkr[l]) * HID + wc4);
    };
    auto store_tiles = [&](int b) {
        uint32_t* Xs = XsBase + b * 4608;
        uint32_t* Ws = WsBase + b * 2304;
#pragma unroll
        for (int l = 0; l < 4; l++) {
            uint4 u;
            u.x = f2tf32(xr[l].x); u.y = f2tf32(xr[l].y);
            u.z = f2tf32(xr[l].z); u.w = f2tf32(xr[l].w);
            *(uint4*)(Xs + xrow[l] * 36 + xc4) = u;
        }
#pragma unroll
        for (int l = 0; l < 2; l++) {
            uint4 u;
            u.x = f2tf32(wr[l].x); u.y = f2tf32(wr[l].y);
            u.z = f2tf32(wr[l].z); u.w = f2tf32(wr[l].w);
            *(uint4*)(Ws + wkr[l] * 72 + wc4) = u;
        }
    };

    float c1[2][4][4];
#pragma unroll
    for (int m = 0; m < 2; m++)
#pragma unroll
        for (int n = 0; n < 4; n++)
#pragma unroll
            for (int i = 0; i < 4; i++) c1[m][n][i] = 0.0f;

    load_tiles(0);
    store_tiles(0);
    __syncthreads();

#pragma unroll 1
    for (int cc = 0; cc < NCHUNK; cc++) {
        if (cc + 1 < NCHUNK) load_tiles(cc + 1);

        const uint32_t* Xs = XsBase + (cc & 1) * 4608;
        const uint32_t* Ws = WsBase + (cc & 1) * 2304;
#pragma unroll
        for (int ka = 0; ka < 4; ka++) {
            const int k0 = ka * 8;
            uint32_t a[2][4];
#pragma unroll
            for (int m = 0; m < 2; m++) {
                int row = wm * 32 + m * 16;
                a[m][0] = Xs[(row + g    ) * 36 + k0 + tq];
                a[m][1] = Xs[(row + g + 8) * 36 + k0 + tq];
                a[m][2] = Xs[(row + g    ) * 36 + k0 + tq + 4];
                a[m][3] = Xs[(row + g + 8) * 36 + k0 + tq + 4];
            }
            uint32_t b[4][2];
#pragma unroll
            for (int n = 0; n < 4; n++) {
                int col = wn * 32 + n * 8 + g;
                b[n][0] = Ws[(k0 + tq    ) * 72 + col];
                b[n][1] = Ws[(k0 + tq + 4) * 72 + col];
            }
#pragma unroll
            for (int m = 0; m < 2; m++)
#pragma unroll
                for (int n = 0; n < 4; n++)
                    mma_tf32(c1[m][n], a[m], b[n]);
        }

        if (cc + 1 < NCHUNK) store_tiles((cc + 1) & 1);
        __syncthreads();
    }

    // bias + relu -> fp16 pairs into H2
#pragma unroll
    for (int n = 0; n < 4; n++) {
        float2 bb = *(const float2*)(b1 + wn * 32 + n * 8 + 2 * tq);
        int colp = wn * 16 + n * 4 + tq;
#pragma unroll
        for (int m = 0; m < 2; m++) {
            int row = wm * 32 + m * 16 + g;
            float h0 = fmaxf(c1[m][n][0] + bb.x, 0.f);
            float h1 = fmaxf(c1[m][n][1] + bb.y, 0.f);
            float h2 = fmaxf(c1[m][n][2] + bb.x, 0.f);
            float h3 = fmaxf(c1[m][n][3] + bb.y, 0.f);
            __half2 p0 = __floats2half2_rn(h0, h1);
            __half2 p1 = __floats2half2_rn(h2, h3);
            H2[row    ][colp] = *(uint32_t*)&p0;
            H2[row + 8][colp] = *(uint32_t*)&p1;
        }
    }
    // W2 -> fp16 k-pair layout
#pragma unroll
    for (int l = 0; l < 8; l++) {
        int idx = t + l * 256;
        int kp  = idx >> 6;
        int n   = idx & 63;
        float w0 = W2[(size_t)(2 * kp    ) * NCLS + n];
        float w1 = W2[(size_t)(2 * kp + 1) * NCLS + n];
        __half2 p = __floats2half2_rn(w0, w1);
        W2p[kp][n] = *(uint32_t*)&p;
    }
    __syncthreads();

    float c2[2][4][4];
#pragma unroll
    for (int m = 0; m < 2; m++)
#pragma unroll
        for (int n = 0; n < 4; n++)
#pragma unroll
            for (int i = 0; i < 4; i++) c2[m][n][i] = 0.0f;

#pragma unroll
    for (int ka = 0; ka < 4; ka++) {
        const int kp = ka * 8;
        uint32_t a[2][4];
#pragma unroll
        for (int m = 0; m < 2; m++) {
            int row = wm * 32 + m * 16;
            a[m][0] = H2[row + g    ][kp + tq];
            a[m][1] = H2[row + g + 8][kp + tq];
            a[m][2] = H2[row + g    ][kp + tq + 4];
            a[m][3] = H2[row + g + 8][kp + tq + 4];
        }
        uint32_t b[4][2];
#pragma unroll
        for (int n = 0; n < 4; n++) {
            int col = wn * 32 + n * 8 + g;
            b[n][0] = W2p[kp + tq    ][col];
            b[n][1] = W2p[kp + tq + 4][col];
        }
#pragma unroll
        for (int m = 0; m < 2; m++)
#pragma unroll
            for (int n = 0; n < 4; n++)
                mma_f16(c2[m][n], a[m], b[n]);
    }

    // + b2, store logits as fp16
    __half2* lg2 = (__half2*)g_logits_h;
#pragma unroll
    for (int n = 0; n < 4; n++) {
        float2 bb = *(const float2*)(b2 + wn * 32 + n * 8 + 2 * tq);
        int colp = wn * 16 + n * 4 + tq;
#pragma unroll
        for (int m = 0; m < 2; m++) {
            int row = rb + wm * 32 + m * 16 + g;
            if (row < N_NODES)
                lg2[(size_t)row * 32 + colp] =
                    __floats2half2_rn(c2[m][n][0] + bb.x, c2[m][n][1] + bb.y);
            if (row + 8 < N_NODES)
                lg2[(size_t)(row + 8) * 32 + colp] =
                    __floats2half2_rn(c2[m][n][2] + bb.x, c2[m][n][3] + bb.y);
        }
    }
}

// ---------------------------------------------------------------------------
// CSR build: histogram -> scan -> scatter
// ---------------------------------------------------------------------------
__global__ __launch_bounds__(256) void hist_k(const int* __restrict__ rows, int E)
{
    int e = blockIdx.x * 256 + threadIdx.x;
    if (e < E) atomicAdd(&g_cnt[rows[e]], 1);
}

__global__ __launch_bounds__(256) void scan1_k(int n)
{
    __shared__ int wsum[8];
    const int t = threadIdx.x, b = blockIdx.x;
    const int base = b * 1024 + t * 4;
    int v0 = 0, v1 = 0, v2 = 0, v3 = 0;
    if (base + 0 < n) v0 = g_cnt[base + 0];
    if (base + 1 < n) v1 = g_cnt[base + 1];
    if (base + 2 < n) v2 = g_cnt[base + 2];
    if (base + 3 < n) v3 = g_cnt[base + 3];
    const int tsum = v0 + v1 + v2 + v3;
    const int lane = t & 31, w = t >> 5;
    int inc = tsum;
#pragma unroll
    for (int d = 1; d < 32; d <<= 1) {
        int y = __shfl_up_sync(0xffffffffu, inc, d);
        if (lane >= d) inc += y;
    }
    if (lane == 31) wsum[w] = inc;
    __syncthreads();
    if (t < 8) {
        int x = wsum[t];
#pragma unroll
        for (int d = 1; d < 8; d <<= 1) {
            int y = __shfl_up_sync(0xffu, x, d);
            if (t >= d) x += y;
        }
        wsum[t] = x;
    }
    __syncthreads();
    const int wprefix = (w == 0) ? 0 : wsum[w - 1];
    const int texcl = wprefix + inc - tsum;
    if (base + 0 < n) g_off[base + 0] = texcl;
    if (base + 1 < n) g_off[base + 1] = texcl + v0;
    if (base + 2 < n) g_off[base + 2] = texcl + v0 + v1;
    if (base + 3 < n) g_off[base + 3] = texcl + v0 + v1 + v2;
    if (t == 255) g_bsum[b] = wsum[7];
}

__global__ __launch_bounds__(128) void scan2_k(int nb)
{
    __shared__ int wsum[4];
    const int t = threadIdx.x;
    int x0 = (t < nb) ? g_bsum[t] : 0;
    const int lane = t & 31, w = t >> 5;
    int x = x0;
#pragma unroll
    for (int d = 1; d < 32; d <<= 1) {
        int y = __shfl_up_sync(0xffffffffu, x, d);
        if (lane >= d) x += y;
    }
    if (lane == 31) wsum[w] = x;
    __syncthreads();
    if (t < 4) {
        int y = wsum[t];
#pragma unroll
        for (int d = 1; d < 4; d <<= 1) {
            int z = __shfl_up_sync(0xfu, y, d);
            if (t >= d) y += z;
        }
        wsum[t] = y;
    }
    __syncthreads();
    const int wprefix = (w == 0) ? 0 : wsum[w - 1];
    if (t < nb) g_bsum[t] = wprefix + x - x0;   // exclusive
}

__global__ __launch_bounds__(256) void scan3_k(int n)
{
    int i = blockIdx.x * 256 + threadIdx.x;
    if (i < n) {
        int o = g_off[i] + g_bsum[i >> 10];
        g_off[i] = o;
        g_run[i] = o;
    }
}

__global__ __launch_bounds__(256) void build_k(
    const int* __restrict__ rows, const int* __restrict__ cols,
    const float* __restrict__ vals, int E)
{
    int e = blockIdx.x * 256 + threadIdx.x;
    if (e >= E) return;
    int r = rows[e];
    int p = atomicAdd(&g_run[r], 1);
    g_epack[p] = make_int2(cols[e], __float_as_int(vals[e]));
}

// ---------------------------------------------------------------------------
// Reduce: one warp per node; float2 accumulators in registers (atomic-free).
// ---------------------------------------------------------------------------
__global__ __launch_bounds__(256) void reduce_k(float* __restrict__ out)
{
    const int wid  = threadIdx.x >> 5;
    const int lane = threadIdx.x & 31;
    const int n    = blockIdx.x * 8 + wid;
    if (n >= N_NODES) return;

    const int s = g_off[n];
    const int m = g_cnt[n];
    const __half2* __restrict__ lg = (const __half2*)g_logits_h;

    float ax = 0.f, ay = 0.f;
    int p = s;
    const int end = s + m;
#pragma unroll 1
    for (; p + 4 <= end; p += 4) {
        int2 e0 = __ldg(&g_epack[p + 0]);
        int2 e1 = __ldg(&g_epack[p + 1]);
        int2 e2 = __ldg(&g_epack[p + 2]);
        int2 e3 = __ldg(&g_epack[p + 3]);
        float2 f0 = __half22float2(lg[(size_t)e0.x * 32 + lane]);
        float2 f1 = __half22float2(lg[(size_t)e1.x * 32 + lane]);
        float2 f2 = __half22float2(lg[(size_t)e2.x * 32 + lane]);
        float2 f3 = __half22float2(lg[(size_t)e3.x * 32 + lane]);
        float v0 = __int_as_float(e0.y), v1 = __int_as_float(e1.y);
        float v2 = __int_as_float(e2.y), v3 = __int_as_float(e3.y);
        ax = fmaf(v0, f0.x, ax); ay = fmaf(v0, f0.y, ay);
        ax = fmaf(v1, f1.x, ax); ay = fmaf(v1, f1.y, ay);
        ax = fmaf(v2, f2.x, ax); ay = fmaf(v2, f2.y, ay);
        ax = fmaf(v3, f3.x, ax); ay = fmaf(v3, f3.y, ay);
    }
#pragma unroll 1
    for (; p < end; p++) {
        int2 e0 = __ldg(&g_epack[p]);
        float2 f0 = __half22float2(lg[(size_t)e0.x * 32 + lane]);
        float v0 = __int_as_float(e0.y);
        ax = fmaf(v0, f0.x, ax); ay = fmaf(v0, f0.y, ay);
    }

    float2 o; o.x = ax; o.y = ay;
    *(float2*)(out + (size_t)n * NCLS + 2 * lane) = o;
}

// ---------------------------------------------------------------------------
extern "C" void kernel_launch(void* const* d_in, const int* in_sizes, int n_in,
                              void* d_out, int out_size)
{
    const float* X    = (const float*)d_in[0];
    const int*   erow = (const int*)  d_in[1];
    const int*   ecol = (const int*)  d_in[2];
    const float* ev   = (const float*)d_in[3];
    const float* W1   = (const float*)d_in[4];
    const float* b1   = (const float*)d_in[5];
    const float* W2   = (const float*)d_in[6];
    const float* b2   = (const float*)d_in[7];
    float* out = (float*)d_out;
    const int E = in_sizes[1];

    void* cnt_ptr = nullptr;
    cudaGetSymbolAddress(&cnt_ptr, g_cnt);
    cudaMemsetAsync(cnt_ptr, 0, N_NODES * sizeof(int));

    const int eb = (E + 255) / 256;
    hist_k <<<eb, 256>>>(erow, E);
    scan1_k<<<SCAN_NB, 256>>>(N_NODES);
    scan2_k<<<1, 128>>>(SCAN_NB);
    scan3_k<<<(N_NODES + 255) / 256, 256>>>(N_NODES);
    build_k<<<eb, 256>>>(erow, ecol, ev, E);

    mlp_mma<<<(N_NODES + BM - 1) / BM, 256>>>(X, W1, b1, W2, b2);

    reduce_k<<<(N_NODES + 7) / 8, 256>>>(out);
}

// round 10
// speedup vs baseline: 1.9382x; 1.1055x over previous
#include <cuda_runtime.h>
#include <cuda_fp16.h>
#include <stdint.h>

#define N_NODES 100000
#define F_IN    512
#define HID     64
#define NCLS    64
#define BM      128
#define KCH     32
#define NCHUNK  (F_IN / KCH)   // 16
#define MAX_E   3200000
#define SCAN_NB ((N_NODES + 1023) / 1024)   // 98

// fp16 logits scratch [N_NODES, 64] = 12.8 MB.
__device__ __align__(256) __half g_logits_h[(size_t)N_NODES * NCLS];
// CSR machinery
__device__ int  g_cnt[N_NODES];
__device__ int  g_off[N_NODES];
__device__ int  g_run[N_NODES];
__device__ int  g_bsum[SCAN_NB];
__device__ __align__(16) int2 g_epack[MAX_E];   // (col, val bits) sorted by row

__device__ __forceinline__ void mma_f16(float* c, const uint32_t* a, const uint32_t* b) {
    asm volatile("mma.sync.aligned.m16n8k16.row.col.f32.f16.f16.f32 "
        "{%0,%1,%2,%3}, {%4,%5,%6,%7}, {%8,%9}, {%0,%1,%2,%3};\n"
        : "+f"(c[0]), "+f"(c[1]), "+f"(c[2]), "+f"(c[3])
        : "r"(a[0]), "r"(a[1]), "r"(a[2]), "r"(a[3]), "r"(b[0]), "r"(b[1]));
}

// ---------------------------------------------------------------------------
// Fused MLP, both GEMMs fp16 mma (fp32 accum; fp16 mantissa == tf32 mantissa).
//   h = relu(X @ W1 + b1); logits = h @ W2 + b2 -> fp16 store
// Block: 128 rows, 8 warps 4(M)x2(N); warp tile 32x32.
// ---------------------------------------------------------------------------
__global__ __launch_bounds__(256) void mlp_mma(
    const float* __restrict__ X,
    const float* __restrict__ W1,
    const float* __restrict__ b1,
    const float* __restrict__ W2,
    const float* __restrict__ b2)
{
    // Phase 1: Xh 2x[128][20] (half2 words), Wp 2x[16][72].
    // Phase 2 overlay: H2 [128][36], W2p [32][72].
    __shared__ __align__(16) uint32_t smem[5120 + 2304];
    uint32_t* XsBase = smem;            // +b*2560
    uint32_t* WsBase = smem + 5120;     // +b*1152
    uint32_t (*H2)[36]  = (uint32_t(*)[36])smem;
    uint32_t (*W2p)[72] = (uint32_t(*)[72])(smem + 5120);

    const int t    = threadIdx.x;
    const int lane = t & 31;
    const int wid  = t >> 5;
    const int wm   = wid & 3;
    const int wn   = wid >> 2;
    const int g    = lane >> 2;
    const int tq   = lane & 3;
    const int rb   = blockIdx.x * BM;

    const int xrow[4] = { (t) >> 3, (t + 256) >> 3, (t + 512) >> 3, (t + 768) >> 3 };
    const int xc4     = (t & 7) * 4;     // k offset (floats)
    const int wkp     = t >> 4;          // k-pair row 0..15
    const int wc4     = (t & 15) * 4;    // n offset

    float4 xr[4], wrA, wrB;

    auto load_tiles = [&](int cc) {
        const int kb = cc * KCH;
#pragma unroll
        for (int l = 0; l < 4; l++) {
            int grow = rb + xrow[l];
            xr[l] = (grow < N_NODES)
                  ? *(const float4*)(X + (size_t)grow * F_IN + kb + xc4)
                  : make_float4(0.f, 0.f, 0.f, 0.f);
        }
        wrA = *(const float4*)(W1 + (size_t)(kb + 2 * wkp    ) * HID + wc4);
        wrB = *(const float4*)(W1 + (size_t)(kb + 2 * wkp + 1) * HID + wc4);
    };
    auto store_tiles = [&](int b) {
        uint32_t* Xs = XsBase + b * 2560;
        uint32_t* Wp = WsBase + b * 1152;
#pragma unroll
        for (int l = 0; l < 4; l++) {
            __half2 h0 = __floats2half2_rn(xr[l].x, xr[l].y);
            __half2 h1 = __floats2half2_rn(xr[l].z, xr[l].w);
            uint2 u; u.x = *(uint32_t*)&h0; u.y = *(uint32_t*)&h1;
            *(uint2*)(Xs + xrow[l] * 20 + (xc4 >> 1)) = u;
        }
        __half2 p0 = __floats2half2_rn(wrA.x, wrB.x);
        __half2 p1 = __floats2half2_rn(wrA.y, wrB.y);
        __half2 p2 = __floats2half2_rn(wrA.z, wrB.z);
        __half2 p3 = __floats2half2_rn(wrA.w, wrB.w);
        uint4 u; u.x = *(uint32_t*)&p0; u.y = *(uint32_t*)&p1;
        u.z = *(uint32_t*)&p2; u.w = *(uint32_t*)&p3;
        *(uint4*)(Wp + wkp * 72 + wc4) = u;
    };

    float c1[2][4][4];
#pragma unroll
    for (int m = 0; m < 2; m++)
#pragma unroll
        for (int n = 0; n < 4; n++)
#pragma unroll
            for (int i = 0; i < 4; i++) c1[m][n][i] = 0.0f;

    load_tiles(0);
    store_tiles(0);
    __syncthreads();

#pragma unroll 1
    for (int cc = 0; cc < NCHUNK; cc++) {
        if (cc + 1 < NCHUNK) load_tiles(cc + 1);

        const uint32_t* Xs = XsBase + (cc & 1) * 2560;
        const uint32_t* Wp = WsBase + (cc & 1) * 1152;
#pragma unroll
        for (int ka = 0; ka < 2; ka++) {
            const int kp = ka * 8;       // half2-pair base (16 k per step)
            uint32_t a[2][4];
#pragma unroll
            for (int m = 0; m < 2; m++) {
                int row = wm * 32 + m * 16;
                a[m][0] = Xs[(row + g    ) * 20 + kp + tq];
                a[m][1] = Xs[(row + g + 8) * 20 + kp + tq];
                a[m][2] = Xs[(row + g    ) * 20 + kp + tq + 4];
                a[m][3] = Xs[(row + g + 8) * 20 + kp + tq + 4];
            }
            uint32_t b[4][2];
#pragma unroll
            for (int n = 0; n < 4; n++) {
                int col = wn * 32 + n * 8 + g;
                b[n][0] = Wp[(kp + tq    ) * 72 + col];
                b[n][1] = Wp[(kp + tq + 4) * 72 + col];
            }
#pragma unroll
            for (int m = 0; m < 2; m++)
#pragma unroll
                for (int n = 0; n < 4; n++)
                    mma_f16(c1[m][n], a[m], b[n]);
        }

        if (cc + 1 < NCHUNK) store_tiles((cc + 1) & 1);
        __syncthreads();
    }

    // bias + relu -> fp16 pairs into H2
#pragma unroll
    for (int n = 0; n < 4; n++) {
        float2 bb = *(const float2*)(b1 + wn * 32 + n * 8 + 2 * tq);
        int colp = wn * 16 + n * 4 + tq;
#pragma unroll
        for (int m = 0; m < 2; m++) {
            int row = wm * 32 + m * 16 + g;
            float h0 = fmaxf(c1[m][n][0] + bb.x, 0.f);
            float h1 = fmaxf(c1[m][n][1] + bb.y, 0.f);
            float h2 = fmaxf(c1[m][n][2] + bb.x, 0.f);
            float h3 = fmaxf(c1[m][n][3] + bb.y, 0.f);
            __half2 p0 = __floats2half2_rn(h0, h1);
            __half2 p1 = __floats2half2_rn(h2, h3);
            H2[row    ][colp] = *(uint32_t*)&p0;
            H2[row + 8][colp] = *(uint32_t*)&p1;
        }
    }
    // W2 -> fp16 k-pair layout
#pragma unroll
    for (int l = 0; l < 8; l++) {
        int idx = t + l * 256;
        int kp  = idx >> 6;
        int n   = idx & 63;
        float w0 = W2[(size_t)(2 * kp    ) * NCLS + n];
        float w1 = W2[(size_t)(2 * kp + 1) * NCLS + n];
        __half2 p = __floats2half2_rn(w0, w1);
        W2p[kp][n] = *(uint32_t*)&p;
    }
    __syncthreads();

    float c2[2][4][4];
#pragma unroll
    for (int m = 0; m < 2; m++)
#pragma unroll
        for (int n = 0; n < 4; n++)
#pragma unroll
            for (int i = 0; i < 4; i++) c2[m][n][i] = 0.0f;

#pragma unroll
    for (int ka = 0; ka < 4; ka++) {
        const int kp = ka * 8;
        uint32_t a[2][4];
#pragma unroll
        for (int m = 0; m < 2; m++) {
            int row = wm * 32 + m * 16;
            a[m][0] = H2[row + g    ][kp + tq];
            a[m][1] = H2[row + g + 8][kp + tq];
            a[m][2] = H2[row + g    ][kp + tq + 4];
            a[m][3] = H2[row + g + 8][kp + tq + 4];
        }
        uint32_t b[4][2];
#pragma unroll
        for (int n = 0; n < 4; n++) {
            int col = wn * 32 + n * 8 + g;
            b[n][0] = W2p[kp + tq    ][col];
            b[n][1] = W2p[kp + tq + 4][col];
        }
#pragma unroll
        for (int m = 0; m < 2; m++)
#pragma unroll
            for (int n = 0; n < 4; n++)
                mma_f16(c2[m][n], a[m], b[n]);
    }

    // + b2, store logits as fp16
    __half2* lg2 = (__half2*)g_logits_h;
#pragma unroll
    for (int n = 0; n < 4; n++) {
        float2 bb = *(const float2*)(b2 + wn * 32 + n * 8 + 2 * tq);
        int colp = wn * 16 + n * 4 + tq;
#pragma unroll
        for (int m = 0; m < 2; m++) {
            int row = rb + wm * 32 + m * 16 + g;
            if (row < N_NODES)
                lg2[(size_t)row * 32 + colp] =
                    __floats2half2_rn(c2[m][n][0] + bb.x, c2[m][n][1] + bb.y);
            if (row + 8 < N_NODES)
                lg2[(size_t)(row + 8) * 32 + colp] =
                    __floats2half2_rn(c2[m][n][2] + bb.x, c2[m][n][3] + bb.y);
        }
    }
}

// ---------------------------------------------------------------------------
// CSR build: histogram -> scan -> scatter
// ---------------------------------------------------------------------------
__global__ __launch_bounds__(256) void hist_k(const int* __restrict__ rows, int E)
{
    int e = blockIdx.x * 256 + threadIdx.x;
    if (e < E) atomicAdd(&g_cnt[rows[e]], 1);
}

__global__ __launch_bounds__(256) void scan1_k(int n)
{
    __shared__ int wsum[8];
    const int t = threadIdx.x, b = blockIdx.x;
    const int base = b * 1024 + t * 4;
    int v0 = 0, v1 = 0, v2 = 0, v3 = 0;
    if (base + 0 < n) v0 = g_cnt[base + 0];
    if (base + 1 < n) v1 = g_cnt[base + 1];
    if (base + 2 < n) v2 = g_cnt[base + 2];
    if (base + 3 < n) v3 = g_cnt[base + 3];
    const int tsum = v0 + v1 + v2 + v3;
    const int lane = t & 31, w = t >> 5;
    int inc = tsum;
#pragma unroll
    for (int d = 1; d < 32; d <<= 1) {
        int y = __shfl_up_sync(0xffffffffu, inc, d);
        if (lane >= d) inc += y;
    }
    if (lane == 31) wsum[w] = inc;
    __syncthreads();
    if (t < 8) {
        int x = wsum[t];
#pragma unroll
        for (int d = 1; d < 8; d <<= 1) {
            int y = __shfl_up_sync(0xffu, x, d);
            if (t >= d) x += y;
        }
        wsum[t] = x;
    }
    __syncthreads();
    const int wprefix = (w == 0) ? 0 : wsum[w - 1];
    const int texcl = wprefix + inc - tsum;
    if (base + 0 < n) g_off[base + 0] = texcl;
    if (base + 1 < n) g_off[base + 1] = texcl + v0;
    if (base + 2 < n) g_off[base + 2] = texcl + v0 + v1;
    if (base + 3 < n) g_off[base + 3] = texcl + v0 + v1 + v2;
    if (t == 255) g_bsum[b] = wsum[7];
}

__global__ __launch_bounds__(128) void scan2_k(int nb)
{
    __shared__ int wsum[4];
    const int t = threadIdx.x;
    int x0 = (t < nb) ? g_bsum[t] : 0;
    const int lane = t & 31, w = t >> 5;
    int x = x0;
#pragma unroll
    for (int d = 1; d < 32; d <<= 1) {
        int y = __shfl_up_sync(0xffffffffu, x, d);
        if (lane >= d) x += y;
    }
    if (lane == 31) wsum[w] = x;
    __syncthreads();
    if (t < 4) {
        int y = wsum[t];
#pragma unroll
        for (int d = 1; d < 4; d <<= 1) {
            int z = __shfl_up_sync(0xfu, y, d);
            if (t >= d) y += z;
        }
        wsum[t] = y;
    }
    __syncthreads();
    const int wprefix = (w == 0) ? 0 : wsum[w - 1];
    if (t < nb) g_bsum[t] = wprefix + x - x0;   // exclusive
}

__global__ __launch_bounds__(256) void scan3_k(int n)
{
    int i = blockIdx.x * 256 + threadIdx.x;
    if (i < n) {
        int o = g_off[i] + g_bsum[i >> 10];
        g_off[i] = o;
        g_run[i] = o;
    }
}

__global__ __launch_bounds__(256) void build_k(
    const int* __restrict__ rows, const int* __restrict__ cols,
    const float* __restrict__ vals, int E)
{
    int e = blockIdx.x * 256 + threadIdx.x;
    if (e >= E) return;
    int r = rows[e];
    int p = atomicAdd(&g_run[r], 1);
    g_epack[p] = make_int2(cols[e], __float_as_int(vals[e]));
}

// ---------------------------------------------------------------------------
// Reduce: one warp per node; float2 accumulators in registers (atomic-free).
// ---------------------------------------------------------------------------
__global__ __launch_bounds__(256) void reduce_k(float* __restrict__ out)
{
    const int wid  = threadIdx.x >> 5;
    const int lane = threadIdx.x & 31;
    const int n    = blockIdx.x * 8 + wid;
    if (n >= N_NODES) return;

    const int s = g_off[n];
    const int m = g_cnt[n];
    const __half2* __restrict__ lg = (const __half2*)g_logits_h;

    float ax = 0.f, ay = 0.f;
    int p = s;
    const int end = s + m;
#pragma unroll 1
    for (; p + 4 <= end; p += 4) {
        int2 e0 = __ldg(&g_epack[p + 0]);
        int2 e1 = __ldg(&g_epack[p + 1]);
        int2 e2 = __ldg(&g_epack[p + 2]);
        int2 e3 = __ldg(&g_epack[p + 3]);
        float2 f0 = __half22float2(lg[(size_t)e0.x * 32 + lane]);
        float2 f1 = __half22float2(lg[(size_t)e1.x * 32 + lane]);
        float2 f2 = __half22float2(lg[(size_t)e2.x * 32 + lane]);
        float2 f3 = __half22float2(lg[(size_t)e3.x * 32 + lane]);
        float v0 = __int_as_float(e0.y), v1 = __int_as_float(e1.y);
        float v2 = __int_as_float(e2.y), v3 = __int_as_float(e3.y);
        ax = fmaf(v0, f0.x, ax); ay = fmaf(v0, f0.y, ay);
        ax = fmaf(v1, f1.x, ax); ay = fmaf(v1, f1.y, ay);
        ax = fmaf(v2, f2.x, ax); ay = fmaf(v2, f2.y, ay);
        ax = fmaf(v3, f3.x, ax); ay = fmaf(v3, f3.y, ay);
    }
#pragma unroll 1
    for (; p < end; p++) {
        int2 e0 = __ldg(&g_epack[p]);
        float2 f0 = __half22float2(lg[(size_t)e0.x * 32 + lane]);
        float v0 = __int_as_float(e0.y);
        ax = fmaf(v0, f0.x, ax); ay = fmaf(v0, f0.y, ay);
    }

    float2 o; o.x = ax; o.y = ay;
    *(float2*)(out + (size_t)n * NCLS + 2 * lane) = o;
}

// ---------------------------------------------------------------------------
// Launch: fork the CSR-build chain onto a side stream so it overlaps the MLP.
// Event fork/join is the documented way to build parallel branches under
// stream capture; the same calls also run correctly in eager mode.
// ---------------------------------------------------------------------------
extern "C" void kernel_launch(void* const* d_in, const int* in_sizes, int n_in,
                              void* d_out, int out_size)
{
    const float* X    = (const float*)d_in[0];
    const int*   erow = (const int*)  d_in[1];
    const int*   ecol = (const int*)  d_in[2];
    const float* ev   = (const float*)d_in[3];
    const float* W1   = (const float*)d_in[4];
    const float* b1   = (const float*)d_in[5];
    const float* W2   = (const float*)d_in[6];
    const float* b2   = (const float*)d_in[7];
    float* out = (float*)d_out;
    const int E = in_sizes[1];

    cudaStream_t s2;
    cudaEvent_t evFork, evJoin;
    cudaStreamCreateWithFlags(&s2, cudaStreamNonBlocking);
    cudaEventCreateWithFlags(&evFork, cudaEventDisableTiming);
    cudaEventCreateWithFlags(&evJoin, cudaEventDisableTiming);

    // Fork: s2 depends on the capture-origin stream state.
    cudaEventRecord(evFork, 0);
    cudaStreamWaitEvent(s2, evFork, 0);

    // Branch A (s2): CSR build chain.
    void* cnt_ptr = nullptr;
    cudaGetSymbolAddress(&cnt_ptr, g_cnt);
    cudaMemsetAsync(cnt_ptr, 0, N_NODES * sizeof(int), s2);
    const int eb = (E + 255) / 256;
    hist_k <<<eb, 256, 0, s2>>>(erow, E);
    scan1_k<<<SCAN_NB, 256, 0, s2>>>(N_NODES);
    scan2_k<<<1, 128, 0, s2>>>(SCAN_NB);
    scan3_k<<<(N_NODES + 255) / 256, 256, 0, s2>>>(N_NODES);
    build_k<<<eb, 256, 0, s2>>>(erow, ecol, ev, E);
    cudaEventRecord(evJoin, s2);

    // Branch B (origin stream): MLP.
    mlp_mma<<<(N_NODES + BM - 1) / BM, 256>>>(X, W1, b1, W2, b2);

    // Join, then reduce.
    cudaStreamWaitEvent(0, evJoin, 0);
    reduce_k<<<(N_NODES + 7) / 8, 256>>>(out);
}

// round 11
// speedup vs baseline: 1.9530x; 1.0076x over previous
#include <cuda_runtime.h>
#include <cuda_fp16.h>
#include <stdint.h>

#define N_NODES 100000
#define F_IN    512
#define HID     64
#define NCLS    64
#define BM      128
#define KCH     32
#define NCHUNK  (F_IN / KCH)   // 16
#define MAX_E   3200000
#define SCAN_NB ((N_NODES + 1023) / 1024)   // 98

// fp16 logits scratch [N_NODES, 64] = 12.8 MB (keep L2-resident).
__device__ __align__(256) __half g_logits_h[(size_t)N_NODES * NCLS];
// CSR machinery
__device__ int  g_cnt[N_NODES];
__device__ int  g_off[N_NODES];
__device__ int  g_run[N_NODES];
__device__ int  g_bsum[SCAN_NB];
__device__ __align__(16) int2 g_epack[MAX_E];   // (col, val bits) sorted by row

__device__ __forceinline__ void mma_f16(float* c, const uint32_t* a, const uint32_t* b) {
    asm volatile("mma.sync.aligned.m16n8k16.row.col.f32.f16.f16.f32 "
        "{%0,%1,%2,%3}, {%4,%5,%6,%7}, {%8,%9}, {%0,%1,%2,%3};\n"
        : "+f"(c[0]), "+f"(c[1]), "+f"(c[2]), "+f"(c[3])
        : "r"(a[0]), "r"(a[1]), "r"(a[2]), "r"(a[3]), "r"(b[0]), "r"(b[1]));
}

// ---------------------------------------------------------------------------
// Fused MLP, both GEMMs fp16 mma (fp32 accum).
//   h = relu(X @ W1 + b1); logits = h @ W2 + b2 -> fp16 store
// Block: 128 rows, 8 warps 4(M)x2(N); warp tile 32x32. Double-buffered K loop.
// ---------------------------------------------------------------------------
__global__ __launch_bounds__(256) void mlp_mma(
    const float* __restrict__ X,
    const float* __restrict__ W1,
    const float* __restrict__ b1,
    const float* __restrict__ W2,
    const float* __restrict__ b2)
{
    __shared__ __align__(16) uint32_t smem[5120 + 2304];
    uint32_t* XsBase = smem;            // +b*2560, half2 [128][20]
    uint32_t* WsBase = smem + 5120;     // +b*1152, half2 [16][72]
    uint32_t (*H2)[36]  = (uint32_t(*)[36])smem;
    uint32_t (*W2p)[72] = (uint32_t(*)[72])(smem + 5120);

    const int t    = threadIdx.x;
    const int lane = t & 31;
    const int wid  = t >> 5;
    const int wm   = wid & 3;
    const int wn   = wid >> 2;
    const int g    = lane >> 2;
    const int tq   = lane & 3;
    const int rb   = blockIdx.x * BM;

    const int xrow[4] = { (t) >> 3, (t + 256) >> 3, (t + 512) >> 3, (t + 768) >> 3 };
    const int xc4     = (t & 7) * 4;
    const int wkp     = t >> 4;          // k-pair row 0..15
    const int wc4     = (t & 15) * 4;

    float4 xr[4], wrA, wrB;

    auto load_tiles = [&](int cc) {
        const int kb = cc * KCH;
#pragma unroll
        for (int l = 0; l < 4; l++) {
            int grow = rb + xrow[l];
            xr[l] = (grow < N_NODES)
                  ? *(const float4*)(X + (size_t)grow * F_IN + kb + xc4)
                  : make_float4(0.f, 0.f, 0.f, 0.f);
        }
        wrA = *(const float4*)(W1 + (size_t)(kb + 2 * wkp    ) * HID + wc4);
        wrB = *(const float4*)(W1 + (size_t)(kb + 2 * wkp + 1) * HID + wc4);
    };
    auto store_tiles = [&](int b) {
        uint32_t* Xs = XsBase + b * 2560;
        uint32_t* Wp = WsBase + b * 1152;
#pragma unroll
        for (int l = 0; l < 4; l++) {
            __half2 h0 = __floats2half2_rn(xr[l].x, xr[l].y);
            __half2 h1 = __floats2half2_rn(xr[l].z, xr[l].w);
            uint2 u; u.x = *(uint32_t*)&h0; u.y = *(uint32_t*)&h1;
            *(uint2*)(Xs + xrow[l] * 20 + (xc4 >> 1)) = u;
        }
        __half2 p0 = __floats2half2_rn(wrA.x, wrB.x);
        __half2 p1 = __floats2half2_rn(wrA.y, wrB.y);
        __half2 p2 = __floats2half2_rn(wrA.z, wrB.z);
        __half2 p3 = __floats2half2_rn(wrA.w, wrB.w);
        uint4 u; u.x = *(uint32_t*)&p0; u.y = *(uint32_t*)&p1;
        u.z = *(uint32_t*)&p2; u.w = *(uint32_t*)&p3;
        *(uint4*)(Wp + wkp * 72 + wc4) = u;
    };

    float c1[2][4][4];
#pragma unroll
    for (int m = 0; m < 2; m++)
#pragma unroll
        for (int n = 0; n < 4; n++)
#pragma unroll
            for (int i = 0; i < 4; i++) c1[m][n][i] = 0.0f;

    load_tiles(0);
    store_tiles(0);
    __syncthreads();

#pragma unroll 1
    for (int cc = 0; cc < NCHUNK; cc++) {
        if (cc + 1 < NCHUNK) load_tiles(cc + 1);

        const uint32_t* Xs = XsBase + (cc & 1) * 2560;
        const uint32_t* Wp = WsBase + (cc & 1) * 1152;
#pragma unroll
        for (int ka = 0; ka < 2; ka++) {
            const int kp = ka * 8;
            uint32_t a[2][4];
#pragma unroll
            for (int m = 0; m < 2; m++) {
                int row = wm * 32 + m * 16;
                a[m][0] = Xs[(row + g    ) * 20 + kp + tq];
                a[m][1] = Xs[(row + g + 8) * 20 + kp + tq];
                a[m][2] = Xs[(row + g    ) * 20 + kp + tq + 4];
                a[m][3] = Xs[(row + g + 8) * 20 + kp + tq + 4];
            }
            uint32_t b[4][2];
#pragma unroll
            for (int n = 0; n < 4; n++) {
                int col = wn * 32 + n * 8 + g;
                b[n][0] = Wp[(kp + tq    ) * 72 + col];
                b[n][1] = Wp[(kp + tq + 4) * 72 + col];
            }
#pragma unroll
            for (int m = 0; m < 2; m++)
#pragma unroll
                for (int n = 0; n < 4; n++)
                    mma_f16(c1[m][n], a[m], b[n]);
        }

        if (cc + 1 < NCHUNK) store_tiles((cc + 1) & 1);
        __syncthreads();
    }

    // bias + relu -> fp16 pairs into H2
#pragma unroll
    for (int n = 0; n < 4; n++) {
        float2 bb = *(const float2*)(b1 + wn * 32 + n * 8 + 2 * tq);
        int colp = wn * 16 + n * 4 + tq;
#pragma unroll
        for (int m = 0; m < 2; m++) {
            int row = wm * 32 + m * 16 + g;
            float h0 = fmaxf(c1[m][n][0] + bb.x, 0.f);
            float h1 = fmaxf(c1[m][n][1] + bb.y, 0.f);
            float h2 = fmaxf(c1[m][n][2] + bb.x, 0.f);
            float h3 = fmaxf(c1[m][n][3] + bb.y, 0.f);
            __half2 p0 = __floats2half2_rn(h0, h1);
            __half2 p1 = __floats2half2_rn(h2, h3);
            H2[row    ][colp] = *(uint32_t*)&p0;
            H2[row + 8][colp] = *(uint32_t*)&p1;
        }
    }
    // W2 -> fp16 k-pair layout
#pragma unroll
    for (int l = 0; l < 8; l++) {
        int idx = t + l * 256;
        int kp  = idx >> 6;
        int n   = idx & 63;
        float w0 = W2[(size_t)(2 * kp    ) * NCLS + n];
        float w1 = W2[(size_t)(2 * kp + 1) * NCLS + n];
        __half2 p = __floats2half2_rn(w0, w1);
        W2p[kp][n] = *(uint32_t*)&p;
    }
    __syncthreads();

    float c2[2][4][4];
#pragma unroll
    for (int m = 0; m < 2; m++)
#pragma unroll
        for (int n = 0; n < 4; n++)
#pragma unroll
            for (int i = 0; i < 4; i++) c2[m][n][i] = 0.0f;

#pragma unroll
    for (int ka = 0; ka < 4; ka++) {
        const int kp = ka * 8;
        uint32_t a[2][4];
#pragma unroll
        for (int m = 0; m < 2; m++) {
            int row = wm * 32 + m * 16;
            a[m][0] = H2[row + g    ][kp + tq];
            a[m][1] = H2[row + g + 8][kp + tq];
            a[m][2] = H2[row + g    ][kp + tq + 4];
            a[m][3] = H2[row + g + 8][kp + tq + 4];
        }
        uint32_t b[4][2];
#pragma unroll
        for (int n = 0; n < 4; n++) {
            int col = wn * 32 + n * 8 + g;
            b[n][0] = W2p[kp + tq    ][col];
            b[n][1] = W2p[kp + tq + 4][col];
        }
#pragma unroll
        for (int m = 0; m < 2; m++)
#pragma unroll
            for (int n = 0; n < 4; n++)
                mma_f16(c2[m][n], a[m], b[n]);
    }

    // + b2, store logits as fp16
    __half2* lg2 = (__half2*)g_logits_h;
#pragma unroll
    for (int n = 0; n < 4; n++) {
        float2 bb = *(const float2*)(b2 + wn * 32 + n * 8 + 2 * tq);
        int colp = wn * 16 + n * 4 + tq;
#pragma unroll
        for (int m = 0; m < 2; m++) {
            int row = rb + wm * 32 + m * 16 + g;
            if (row < N_NODES)
                lg2[(size_t)row * 32 + colp] =
                    __floats2half2_rn(c2[m][n][0] + bb.x, c2[m][n][1] + bb.y);
            if (row + 8 < N_NODES)
                lg2[(size_t)(row + 8) * 32 + colp] =
                    __floats2half2_rn(c2[m][n][2] + bb.x, c2[m][n][3] + bb.y);
        }
    }
}

// ---------------------------------------------------------------------------
// CSR build: histogram -> scan -> scatter (4 edges/thread, vectorized)
// ---------------------------------------------------------------------------
__global__ __launch_bounds__(256) void hist_k(const int* __restrict__ rows, int E)
{
    int base = (blockIdx.x * 256 + threadIdx.x) * 4;
    if (base + 3 < E) {
        int4 r = *(const int4*)(rows + base);
        atomicAdd(&g_cnt[r.x], 1);
        atomicAdd(&g_cnt[r.y], 1);
        atomicAdd(&g_cnt[r.z], 1);
        atomicAdd(&g_cnt[r.w], 1);
    } else {
        for (int e = base; e < E; e++) atomicAdd(&g_cnt[rows[e]], 1);
    }
}

__global__ __launch_bounds__(256) void scan1_k(int n)
{
    __shared__ int wsum[8];
    const int t = threadIdx.x, b = blockIdx.x;
    const int base = b * 1024 + t * 4;
    int v0 = 0, v1 = 0, v2 = 0, v3 = 0;
    if (base + 0 < n) v0 = g_cnt[base + 0];
    if (base + 1 < n) v1 = g_cnt[base + 1];
    if (base + 2 < n) v2 = g_cnt[base + 2];
    if (base + 3 < n) v3 = g_cnt[base + 3];
    const int tsum = v0 + v1 + v2 + v3;
    const int lane = t & 31, w = t >> 5;
    int inc = tsum;
#pragma unroll
    for (int d = 1; d < 32; d <<= 1) {
        int y = __shfl_up_sync(0xffffffffu, inc, d);
        if (lane >= d) inc += y;
    }
    if (lane == 31) wsum[w] = inc;
    __syncthreads();
    if (t < 8) {
        int x = wsum[t];
#pragma unroll
        for (int d = 1; d < 8; d <<= 1) {
            int y = __shfl_up_sync(0xffu, x, d);
            if (t >= d) x += y;
        }
        wsum[t] = x;
    }
    __syncthreads();
    const int wprefix = (w == 0) ? 0 : wsum[w - 1];
    const int texcl = wprefix + inc - tsum;
    if (base + 0 < n) g_off[base + 0] = texcl;
    if (base + 1 < n) g_off[base + 1] = texcl + v0;
    if (base + 2 < n) g_off[base + 2] = texcl + v0 + v1;
    if (base + 3 < n) g_off[base + 3] = texcl + v0 + v1 + v2;
    if (t == 255) g_bsum[b] = wsum[7];
}

__global__ __launch_bounds__(128) void scan2_k(int nb)
{
    __shared__ int wsum[4];
    const int t = threadIdx.x;
    int x0 = (t < nb) ? g_bsum[t] : 0;
    const int lane = t & 31, w = t >> 5;
    int x = x0;
#pragma unroll
    for (int d = 1; d < 32; d <<= 1) {
        int y = __shfl_up_sync(0xffffffffu, x, d);
        if (lane >= d) x += y;
    }
    if (lane == 31) wsum[w] = x;
    __syncthreads();
    if (t < 4) {
        int y = wsum[t];
#pragma unroll
        for (int d = 1; d < 4; d <<= 1) {
            int z = __shfl_up_sync(0xfu, y, d);
            if (t >= d) y += z;
        }
        wsum[t] = y;
    }
    __syncthreads();
    const int wprefix = (w == 0) ? 0 : wsum[w - 1];
    if (t < nb) g_bsum[t] = wprefix + x - x0;   // exclusive
}

__global__ __launch_bounds__(256) void scan3_k(int n)
{
    int i = blockIdx.x * 256 + threadIdx.x;
    if (i < n) {
        int o = g_off[i] + g_bsum[i >> 10];
        g_off[i] = o;
        g_run[i] = o;
    }
}

__device__ __forceinline__ void epack_store(int p, int col, float val) {
    int2 e = make_int2(col, __float_as_int(val));
    __stcs(&g_epack[p], e);   // evict-first: don't displace logits in L2
}

__global__ __launch_bounds__(256) void build_k(
    const int* __restrict__ rows, const int* __restrict__ cols,
    const float* __restrict__ vals, int E)
{
    int base = (blockIdx.x * 256 + threadIdx.x) * 4;
    if (base + 3 < E) {
        int4   r = *(const int4*)(rows + base);
        int4   c = *(const int4*)(cols + base);
        float4 v = *(const float4*)(vals + base);
        epack_store(atomicAdd(&g_run[r.x], 1), c.x, v.x);
        epack_store(atomicAdd(&g_run[r.y], 1), c.y, v.y);
        epack_store(atomicAdd(&g_run[r.z], 1), c.z, v.z);
        epack_store(atomicAdd(&g_run[r.w], 1), c.w, v.w);
    } else {
        for (int e = base; e < E; e++)
            epack_store(atomicAdd(&g_run[rows[e]], 1), cols[e], vals[e]);
    }
}

// ---------------------------------------------------------------------------
// Reduce: one warp per node, two 16-lane halves each handling alternate edges.
// One broadcast LDG.64 serves 2 edges; one gather LDG.64 covers 2 full rows.
// shfl_xor(16) combine; 16-lane float4 store. Atomic-free.
// ---------------------------------------------------------------------------
__global__ __launch_bounds__(256) void reduce_k(float* __restrict__ out)
{
    const int wid  = threadIdx.x >> 5;
    const int lane = threadIdx.x & 31;
    const int n    = blockIdx.x * 8 + wid;
    if (n >= N_NODES) return;

    const int s   = g_off[n];
    const int m   = g_cnt[n];
    const int end = s + m;
    const int half = lane >> 4;    // 0 or 1
    const int j    = lane & 15;    // column quad 0..15

    const uint2* __restrict__ lg = (const uint2*)g_logits_h;  // row = 16 uint2

    float a0 = 0.f, a1 = 0.f, a2 = 0.f, a3 = 0.f;
    int p = s + half;

    auto body = [&](int pp) {
        int2 e = __ldcs(&g_epack[pp]);
        uint2 q = lg[(size_t)e.x * 16 + j];
        float v = __int_as_float(e.y);
        float2 f0 = __half22float2(*(const __half2*)&q.x);
        float2 f1 = __half22float2(*(const __half2*)&q.y);
        a0 = fmaf(v, f0.x, a0);
        a1 = fmaf(v, f0.y, a1);
        a2 = fmaf(v, f1.x, a2);
        a3 = fmaf(v, f1.y, a3);
    };

#pragma unroll 1
    for (; p + 2 < end; p += 4) { body(p); body(p + 2); }
#pragma unroll 1
    for (; p < end; p += 2) body(p);

    // combine the two halves (columns identical across halves)
    a0 += __shfl_xor_sync(0xffffffffu, a0, 16);
    a1 += __shfl_xor_sync(0xffffffffu, a1, 16);
    a2 += __shfl_xor_sync(0xffffffffu, a2, 16);
    a3 += __shfl_xor_sync(0xffffffffu, a3, 16);

    if (half == 0) {
        float4 o; o.x = a0; o.y = a1; o.z = a2; o.w = a3;
        __stcs((float4*)(out + (size_t)n * NCLS + j * 4), o);
    }
}

// ---------------------------------------------------------------------------
// Launch: fork the CSR-build chain onto a side stream so it overlaps the MLP.
// ---------------------------------------------------------------------------
extern "C" void kernel_launch(void* const* d_in, const int* in_sizes, int n_in,
                              void* d_out, int out_size)
{
    const float* X    = (const float*)d_in[0];
    const int*   erow = (const int*)  d_in[1];
    const int*   ecol = (const int*)  d_in[2];
    const float* ev   = (const float*)d_in[3];
    const float* W1   = (const float*)d_in[4];
    const float* b1   = (const float*)d_in[5];
    const float* W2   = (const float*)d_in[6];
    const float* b2   = (const float*)d_in[7];
    float* out = (float*)d_out;
    const int E = in_sizes[1];

    cudaStream_t s2;
    cudaEvent_t evFork, evJoin;
    cudaStreamCreateWithFlags(&s2, cudaStreamNonBlocking);
    cudaEventCreateWithFlags(&evFork, cudaEventDisableTiming);
    cudaEventCreateWithFlags(&evJoin, cudaEventDisableTiming);

    cudaEventRecord(evFork, 0);
    cudaStreamWaitEvent(s2, evFork, 0);

    // Branch A (s2): CSR build chain.
    void* cnt_ptr = nullptr;
    cudaGetSymbolAddress(&cnt_ptr, g_cnt);
    cudaMemsetAsync(cnt_ptr, 0, N_NODES * sizeof(int), s2);
    const int eb4 = (E / 4 + 255) / 256;
    hist_k <<<eb4, 256, 0, s2>>>(erow, E);
    scan1_k<<<SCAN_NB, 256, 0, s2>>>(N_NODES);
    scan2_k<<<1, 128, 0, s2>>>(SCAN_NB);
    scan3_k<<<(N_NODES + 255) / 256, 256, 0, s2>>>(N_NODES);
    build_k<<<eb4, 256, 0, s2>>>(erow, ecol, ev, E);
    cudaEventRecord(evJoin, s2);

    // Branch B (origin stream): MLP.
    mlp_mma<<<(N_NODES + BM - 1) / BM, 256>>>(X, W1, b1, W2, b2);

    // Join, then reduce.
    cudaStreamWaitEvent(0, evJoin, 0);
    reduce_k<<<(N_NODES + 7) / 8, 256>>>(out);
}

// round 12
// speedup vs baseline: 2.0830x; 1.0666x over previous
#include <cuda_runtime.h>
#include <cuda_fp16.h>
#include <stdint.h>

#define N_NODES 100000
#define F_IN    512
#define HID     64
#define NCLS    64
#define BM      128
#define KCH     32
#define NCHUNK  (F_IN / KCH)   // 16
#define MAX_E   3200000
#define SCAN_NB ((N_NODES + 1023) / 1024)   // 98

// fp16 logits scratch [N_NODES, 64] = 12.8 MB (keep L2-resident).
__device__ __align__(256) __half g_logits_h[(size_t)N_NODES * NCLS];
// CSR machinery
__device__ int  g_cnt[N_NODES];
__device__ int  g_off[N_NODES];
__device__ int  g_run[N_NODES];
__device__ int  g_bsum[SCAN_NB];
__device__ __align__(16) int2 g_epack[MAX_E];   // (col, val bits) sorted by row

__device__ __forceinline__ void mma_f16(float* c, const uint32_t* a, const uint32_t* b) {
    asm volatile("mma.sync.aligned.m16n8k16.row.col.f32.f16.f16.f32 "
        "{%0,%1,%2,%3}, {%4,%5,%6,%7}, {%8,%9}, {%0,%1,%2,%3};\n"
        : "+f"(c[0]), "+f"(c[1]), "+f"(c[2]), "+f"(c[3])
        : "r"(a[0]), "r"(a[1]), "r"(a[2]), "r"(a[3]), "r"(b[0]), "r"(b[1]));
}

// ---------------------------------------------------------------------------
// Fused MLP, both GEMMs fp16 mma (fp32 accum).
//   h = relu(X @ W1 + b1); logits = h @ W2 + b2 -> fp16 store
// Block: 128 rows, 8 warps 4(M)x2(N); warp tile 32x32. Double-buffered K loop.
// ---------------------------------------------------------------------------
__global__ __launch_bounds__(256) void mlp_mma(
    const float* __restrict__ X,
    const float* __restrict__ W1,
    const float* __restrict__ b1,
    const float* __restrict__ W2,
    const float* __restrict__ b2)
{
    __shared__ __align__(16) uint32_t smem[5120 + 2304];
    uint32_t* XsBase = smem;            // +b*2560, half2 [128][20]
    uint32_t* WsBase = smem + 5120;     // +b*1152, half2 [16][72]
    uint32_t (*H2)[36]  = (uint32_t(*)[36])smem;
    uint32_t (*W2p)[72] = (uint32_t(*)[72])(smem + 5120);

    const int t    = threadIdx.x;
    const int lane = t & 31;
    const int wid  = t >> 5;
    const int wm   = wid & 3;
    const int wn   = wid >> 2;
    const int g    = lane >> 2;
    const int tq   = lane & 3;
    const int rb   = blockIdx.x * BM;

    const int xrow[4] = { (t) >> 3, (t + 256) >> 3, (t + 512) >> 3, (t + 768) >> 3 };
    const int xc4     = (t & 7) * 4;
    const int wkp     = t >> 4;          // k-pair row 0..15
    const int wc4     = (t & 15) * 4;

    float4 xr[4], wrA, wrB;

    auto load_tiles = [&](int cc) {
        const int kb = cc * KCH;
#pragma unroll
        for (int l = 0; l < 4; l++) {
            int grow = rb + xrow[l];
            xr[l] = (grow < N_NODES)
                  ? *(const float4*)(X + (size_t)grow * F_IN + kb + xc4)
                  : make_float4(0.f, 0.f, 0.f, 0.f);
        }
        wrA = *(const float4*)(W1 + (size_t)(kb + 2 * wkp    ) * HID + wc4);
        wrB = *(const float4*)(W1 + (size_t)(kb + 2 * wkp + 1) * HID + wc4);
    };
    auto store_tiles = [&](int b) {
        uint32_t* Xs = XsBase + b * 2560;
        uint32_t* Wp = WsBase + b * 1152;
#pragma unroll
        for (int l = 0; l < 4; l++) {
            __half2 h0 = __floats2half2_rn(xr[l].x, xr[l].y);
            __half2 h1 = __floats2half2_rn(xr[l].z, xr[l].w);
            uint2 u; u.x = *(uint32_t*)&h0; u.y = *(uint32_t*)&h1;
            *(uint2*)(Xs + xrow[l] * 20 + (xc4 >> 1)) = u;
        }
        __half2 p0 = __floats2half2_rn(wrA.x, wrB.x);
        __half2 p1 = __floats2half2_rn(wrA.y, wrB.y);
        __half2 p2 = __floats2half2_rn(wrA.z, wrB.z);
        __half2 p3 = __floats2half2_rn(wrA.w, wrB.w);
        uint4 u; u.x = *(uint32_t*)&p0; u.y = *(uint32_t*)&p1;
        u.z = *(uint32_t*)&p2; u.w = *(uint32_t*)&p3;
        *(uint4*)(Wp + wkp * 72 + wc4) = u;
    };

    float c1[2][4][4];
#pragma unroll
    for (int m = 0; m < 2; m++)
#pragma unroll
        for (int n = 0; n < 4; n++)
#pragma unroll
            for (int i = 0; i < 4; i++) c1[m][n][i] = 0.0f;

    load_tiles(0);
    store_tiles(0);
    __syncthreads();

#pragma unroll 1
    for (int cc = 0; cc < NCHUNK; cc++) {
        if (cc + 1 < NCHUNK) load_tiles(cc + 1);

        const uint32_t* Xs = XsBase + (cc & 1) * 2560;
        const uint32_t* Wp = WsBase + (cc & 1) * 1152;
#pragma unroll
        for (int ka = 0; ka < 2; ka++) {
            const int kp = ka * 8;
            uint32_t a[2][4];
#pragma unroll
            for (int m = 0; m < 2; m++) {
                int row = wm * 32 + m * 16;
                a[m][0] = Xs[(row + g    ) * 20 + kp + tq];
                a[m][1] = Xs[(row + g + 8) * 20 + kp + tq];
                a[m][2] = Xs[(row + g    ) * 20 + kp + tq + 4];
                a[m][3] = Xs[(row + g + 8) * 20 + kp + tq + 4];
            }
            uint32_t b[4][2];
#pragma unroll
            for (int n = 0; n < 4; n++) {
                int col = wn * 32 + n * 8 + g;
                b[n][0] = Wp[(kp + tq    ) * 72 + col];
                b[n][1] = Wp[(kp + tq + 4) * 72 + col];
            }
#pragma unroll
            for (int m = 0; m < 2; m++)
#pragma unroll
                for (int n = 0; n < 4; n++)
                    mma_f16(c1[m][n], a[m], b[n]);
        }

        if (cc + 1 < NCHUNK) store_tiles((cc + 1) & 1);
        __syncthreads();
    }

    // bias + relu -> fp16 pairs into H2
#pragma unroll
    for (int n = 0; n < 4; n++) {
        float2 bb = *(const float2*)(b1 + wn * 32 + n * 8 + 2 * tq);
        int colp = wn * 16 + n * 4 + tq;
#pragma unroll
        for (int m = 0; m < 2; m++) {
            int row = wm * 32 + m * 16 + g;
            float h0 = fmaxf(c1[m][n][0] + bb.x, 0.f);
            float h1 = fmaxf(c1[m][n][1] + bb.y, 0.f);
            float h2 = fmaxf(c1[m][n][2] + bb.x, 0.f);
            float h3 = fmaxf(c1[m][n][3] + bb.y, 0.f);
            __half2 p0 = __floats2half2_rn(h0, h1);
            __half2 p1 = __floats2half2_rn(h2, h3);
            H2[row    ][colp] = *(uint32_t*)&p0;
            H2[row + 8][colp] = *(uint32_t*)&p1;
        }
    }
    // W2 -> fp16 k-pair layout
#pragma unroll
    for (int l = 0; l < 8; l++) {
        int idx = t + l * 256;
        int kp  = idx >> 6;
        int n   = idx & 63;
        float w0 = W2[(size_t)(2 * kp    ) * NCLS + n];
        float w1 = W2[(size_t)(2 * kp + 1) * NCLS + n];
        __half2 p = __floats2half2_rn(w0, w1);
        W2p[kp][n] = *(uint32_t*)&p;
    }
    __syncthreads();

    float c2[2][4][4];
#pragma unroll
    for (int m = 0; m < 2; m++)
#pragma unroll
        for (int n = 0; n < 4; n++)
#pragma unroll
            for (int i = 0; i < 4; i++) c2[m][n][i] = 0.0f;

#pragma unroll
    for (int ka = 0; ka < 4; ka++) {
        const int kp = ka * 8;
        uint32_t a[2][4];
#pragma unroll
        for (int m = 0; m < 2; m++) {
            int row = wm * 32 + m * 16;
            a[m][0] = H2[row + g    ][kp + tq];
            a[m][1] = H2[row + g + 8][kp + tq];
            a[m][2] = H2[row + g    ][kp + tq + 4];
            a[m][3] = H2[row + g + 8][kp + tq + 4];
        }
        uint32_t b[4][2];
#pragma unroll
        for (int n = 0; n < 4; n++) {
            int col = wn * 32 + n * 8 + g;
            b[n][0] = W2p[kp + tq    ][col];
            b[n][1] = W2p[kp + tq + 4][col];
        }
#pragma unroll
        for (int m = 0; m < 2; m++)
#pragma unroll
            for (int n = 0; n < 4; n++)
                mma_f16(c2[m][n], a[m], b[n]);
    }

    // + b2, store logits as fp16
    __half2* lg2 = (__half2*)g_logits_h;
#pragma unroll
    for (int n = 0; n < 4; n++) {
        float2 bb = *(const float2*)(b2 + wn * 32 + n * 8 + 2 * tq);
        int colp = wn * 16 + n * 4 + tq;
#pragma unroll
        for (int m = 0; m < 2; m++) {
            int row = rb + wm * 32 + m * 16 + g;
            if (row < N_NODES)
                lg2[(size_t)row * 32 + colp] =
                    __floats2half2_rn(c2[m][n][0] + bb.x, c2[m][n][1] + bb.y);
            if (row + 8 < N_NODES)
                lg2[(size_t)(row + 8) * 32 + colp] =
                    __floats2half2_rn(c2[m][n][2] + bb.x, c2[m][n][3] + bb.y);
        }
    }
}

// ---------------------------------------------------------------------------
// CSR build: histogram -> scan -> scatter (4 edges/thread, vectorized)
// ---------------------------------------------------------------------------
__global__ __launch_bounds__(256) void hist_k(const int* __restrict__ rows, int E)
{
    int base = (blockIdx.x * 256 + threadIdx.x) * 4;
    if (base + 3 < E) {
        int4 r = *(const int4*)(rows + base);
        atomicAdd(&g_cnt[r.x], 1);
        atomicAdd(&g_cnt[r.y], 1);
        atomicAdd(&g_cnt[r.z], 1);
        atomicAdd(&g_cnt[r.w], 1);
    } else {
        for (int e = base; e < E; e++) atomicAdd(&g_cnt[rows[e]], 1);
    }
}

__global__ __launch_bounds__(256) void scan1_k(int n)
{
    __shared__ int wsum[8];
    const int t = threadIdx.x, b = blockIdx.x;
    const int base = b * 1024 + t * 4;
    int v0 = 0, v1 = 0, v2 = 0, v3 = 0;
    if (base + 0 < n) v0 = g_cnt[base + 0];
    if (base + 1 < n) v1 = g_cnt[base + 1];
    if (base + 2 < n) v2 = g_cnt[base + 2];
    if (base + 3 < n) v3 = g_cnt[base + 3];
    const int tsum = v0 + v1 + v2 + v3;
    const int lane = t & 31, w = t >> 5;
    int inc = tsum;
#pragma unroll
    for (int d = 1; d < 32; d <<= 1) {
        int y = __shfl_up_sync(0xffffffffu, inc, d);
        if (lane >= d) inc += y;
    }
    if (lane == 31) wsum[w] = inc;
    __syncthreads();
    if (t < 8) {
        int x = wsum[t];
#pragma unroll
        for (int d = 1; d < 8; d <<= 1) {
            int y = __shfl_up_sync(0xffu, x, d);
            if (t >= d) x += y;
        }
        wsum[t] = x;
    }
    __syncthreads();
    const int wprefix = (w == 0) ? 0 : wsum[w - 1];
    const int texcl = wprefix + inc - tsum;
    if (base + 0 < n) g_off[base + 0] = texcl;
    if (base + 1 < n) g_off[base + 1] = texcl + v0;
    if (base + 2 < n) g_off[base + 2] = texcl + v0 + v1;
    if (base + 3 < n) g_off[base + 3] = texcl + v0 + v1 + v2;
    if (t == 255) g_bsum[b] = wsum[7];
}

__global__ __launch_bounds__(128) void scan2_k(int nb)
{
    __shared__ int wsum[4];
    const int t = threadIdx.x;
    int x0 = (t < nb) ? g_bsum[t] : 0;
    const int lane = t & 31, w = t >> 5;
    int x = x0;
#pragma unroll
    for (int d = 1; d < 32; d <<= 1) {
        int y = __shfl_up_sync(0xffffffffu, x, d);
        if (lane >= d) x += y;
    }
    if (lane == 31) wsum[w] = x;
    __syncthreads();
    if (t < 4) {
        int y = wsum[t];
#pragma unroll
        for (int d = 1; d < 4; d <<= 1) {
            int z = __shfl_up_sync(0xfu, y, d);
            if (t >= d) y += z;
        }
        wsum[t] = y;
    }
    __syncthreads();
    const int wprefix = (w == 0) ? 0 : wsum[w - 1];
    if (t < nb) g_bsum[t] = wprefix + x - x0;   // exclusive
}

__global__ __launch_bounds__(256) void scan3_k(int n)
{
    int i = blockIdx.x * 256 + threadIdx.x;
    if (i < n) {
        int o = g_off[i] + g_bsum[i >> 10];
        g_off[i] = o;
        g_run[i] = o;
    }
}

__device__ __forceinline__ void epack_store(int p, int col, float val) {
    int2 e = make_int2(col, __float_as_int(val));
    __stcs(&g_epack[p], e);   // evict-first: don't displace logits in L2
}

__global__ __launch_bounds__(256) void build_k(
    const int* __restrict__ rows, const int* __restrict__ cols,
    const float* __restrict__ vals, int E)
{
    int base = (blockIdx.x * 256 + threadIdx.x) * 4;
    if (base + 3 < E) {
        int4   r = *(const int4*)(rows + base);
        int4   c = *(const int4*)(cols + base);
        float4 v = *(const float4*)(vals + base);
        epack_store(atomicAdd(&g_run[r.x], 1), c.x, v.x);
        epack_store(atomicAdd(&g_run[r.y], 1), c.y, v.y);
        epack_store(atomicAdd(&g_run[r.z], 1), c.z, v.z);
        epack_store(atomicAdd(&g_run[r.w], 1), c.w, v.w);
    } else {
        for (int e = base; e < E; e++)
            epack_store(atomicAdd(&g_run[rows[e]], 1), cols[e], vals[e]);
    }
}

// ---------------------------------------------------------------------------
// Reduce: one warp per node, FOUR 8-lane groups, each handling every 4th edge.
// Lane gathers uint4 (16B = 8 fp16 cols); 8 lanes cover the 128B row.
// Epack entry for iteration i+1 is prefetched before issuing gather i
// (edge-list latency off the critical chain; 4 gather chains in flight).
// shfl_xor(8,16) combine; lanes 0-7 store 256B contiguous. Atomic-free.
// ---------------------------------------------------------------------------
__global__ __launch_bounds__(256) void reduce_k(float* __restrict__ out)
{
    const int wid  = threadIdx.x >> 5;
    const int lane = threadIdx.x & 31;
    const int n    = blockIdx.x * 8 + wid;
    if (n >= N_NODES) return;

    const int s   = g_off[n];
    const int m   = g_cnt[n];
    const int end = s + m;
    const int grp = lane >> 3;    // 0..3: which edge stream
    const int j   = lane & 7;     // uint4 index within 64-col row

    const uint4* __restrict__ lg4 = (const uint4*)g_logits_h;  // row = 8 uint4

    float a0 = 0.f, a1 = 0.f, a2 = 0.f, a3 = 0.f;
    float a4 = 0.f, a5 = 0.f, a6 = 0.f, a7 = 0.f;

    int p = s + grp;
    int2 e = (p < end) ? __ldcs(&g_epack[p]) : make_int2(0, 0);

#pragma unroll 1
    while (p < end) {
        const int pn = p + 4;
        int2 en = (pn < end) ? __ldcs(&g_epack[pn]) : make_int2(0, 0);

        uint4 q = lg4[(size_t)e.x * 8 + j];
        float v = __int_as_float(e.y);
        float2 f0 = __half22float2(*(const __half2*)&q.x);
        float2 f1 = __half22float2(*(const __half2*)&q.y);
        float2 f2 = __half22float2(*(const __half2*)&q.z);
        float2 f3 = __half22float2(*(const __half2*)&q.w);
        a0 = fmaf(v, f0.x, a0); a1 = fmaf(v, f0.y, a1);
        a2 = fmaf(v, f1.x, a2); a3 = fmaf(v, f1.y, a3);
        a4 = fmaf(v, f2.x, a4); a5 = fmaf(v, f2.y, a5);
        a6 = fmaf(v, f3.x, a6); a7 = fmaf(v, f3.y, a7);

        e = en; p = pn;
    }

    // combine the four groups (column mapping identical across groups)
#pragma unroll
    for (int d = 8; d <= 16; d <<= 1) {
        a0 += __shfl_xor_sync(0xffffffffu, a0, d);
        a1 += __shfl_xor_sync(0xffffffffu, a1, d);
        a2 += __shfl_xor_sync(0xffffffffu, a2, d);
        a3 += __shfl_xor_sync(0xffffffffu, a3, d);
        a4 += __shfl_xor_sync(0xffffffffu, a4, d);
        a5 += __shfl_xor_sync(0xffffffffu, a5, d);
        a6 += __shfl_xor_sync(0xffffffffu, a6, d);
        a7 += __shfl_xor_sync(0xffffffffu, a7, d);
    }

    if (grp == 0) {
        float4 o0; o0.x = a0; o0.y = a1; o0.z = a2; o0.w = a3;
        float4 o1; o1.x = a4; o1.y = a5; o1.z = a6; o1.w = a7;
        __stcs((float4*)(out + (size_t)n * NCLS + j * 8), o0);
        __stcs((float4*)(out + (size_t)n * NCLS + j * 8 + 4), o1);
    }
}

// ---------------------------------------------------------------------------
// Launch: fork the CSR-build chain onto a side stream so it overlaps the MLP.
// ---------------------------------------------------------------------------
extern "C" void kernel_launch(void* const* d_in, const int* in_sizes, int n_in,
                              void* d_out, int out_size)
{
    const float* X    = (const float*)d_in[0];
    const int*   erow = (const int*)  d_in[1];
    const int*   ecol = (const int*)  d_in[2];
    const float* ev   = (const float*)d_in[3];
    const float* W1   = (const float*)d_in[4];
    const float* b1   = (const float*)d_in[5];
    const float* W2   = (const float*)d_in[6];
    const float* b2   = (const float*)d_in[7];
    float* out = (float*)d_out;
    const int E = in_sizes[1];

    cudaStream_t s2;
    cudaEvent_t evFork, evJoin;
    cudaStreamCreateWithFlags(&s2, cudaStreamNonBlocking);
    cudaEventCreateWithFlags(&evFork, cudaEventDisableTiming);
    cudaEventCreateWithFlags(&evJoin, cudaEventDisableTiming);

    cudaEventRecord(evFork, 0);
    cudaStreamWaitEvent(s2, evFork, 0);

    // Branch A (s2): CSR build chain.
    void* cnt_ptr = nullptr;
    cudaGetSymbolAddress(&cnt_ptr, g_cnt);
    cudaMemsetAsync(cnt_ptr, 0, N_NODES * sizeof(int), s2);
    const int eb4 = (E / 4 + 255) / 256;
    hist_k <<<eb4, 256, 0, s2>>>(erow, E);
    scan1_k<<<SCAN_NB, 256, 0, s2>>>(N_NODES);
    scan2_k<<<1, 128, 0, s2>>>(SCAN_NB);
    scan3_k<<<(N_NODES + 255) / 256, 256, 0, s2>>>(N_NODES);
    build_k<<<eb4, 256, 0, s2>>>(erow, ecol, ev, E);
    cudaEventRecord(evJoin, s2);

    // Branch B (origin stream): MLP.
    mlp_mma<<<(N_NODES + BM - 1) / BM, 256>>>(X, W1, b1, W2, b2);

    // Join, then reduce.
    cudaStreamWaitEvent(0, evJoin, 0);
    reduce_k<<<(N_NODES + 7) / 8, 256>>>(out);
}

// round 13
// speedup vs baseline: 2.1339x; 1.0244x over previous
#include <cuda_runtime.h>
#include <cuda_fp16.h>
#include <stdint.h>

#define N_NODES 100000
#define F_IN    512
#define HID     64
#define NCLS    64
#define BM      128
#define KCH     32
#define NCHUNK  (F_IN / KCH)   // 16
#define MAX_E   3200000
#define SCAN_NB ((N_NODES + 1023) / 1024)   // 98

// fp16 logits scratch [N_NODES, 64] = 12.8 MB (keep L2-resident).
__device__ __align__(256) __half g_logits_h[(size_t)N_NODES * NCLS];
// CSR machinery
__device__ int  g_cnt[N_NODES];
__device__ int  g_off[N_NODES];
__device__ int  g_run[N_NODES];
__device__ int  g_bsum[SCAN_NB];
__device__ __align__(16) int2 g_epack[MAX_E];   // (col, val bits) sorted by row

__device__ __forceinline__ void mma_f16(float* c, const uint32_t* a, const uint32_t* b) {
    asm volatile("mma.sync.aligned.m16n8k16.row.col.f32.f16.f16.f32 "
        "{%0,%1,%2,%3}, {%4,%5,%6,%7}, {%8,%9}, {%0,%1,%2,%3};\n"
        : "+f"(c[0]), "+f"(c[1]), "+f"(c[2]), "+f"(c[3])
        : "r"(a[0]), "r"(a[1]), "r"(a[2]), "r"(a[3]), "r"(b[0]), "r"(b[1]));
}

// ---------------------------------------------------------------------------
// Fused MLP, both GEMMs fp16 mma (fp32 accum).
//   h = relu(X @ W1 + b1); logits = h @ W2 + b2 -> fp16 store
// Block: 128 rows, 8 warps 4(M)x2(N); warp tile 32x32. Double-buffered K loop.
// X is streamed once -> __ldcs (evict-first) to protect L2 for logits/edges.
// ---------------------------------------------------------------------------
__global__ __launch_bounds__(256) void mlp_mma(
    const float* __restrict__ X,
    const float* __restrict__ W1,
    const float* __restrict__ b1,
    const float* __restrict__ W2,
    const float* __restrict__ b2)
{
    __shared__ __align__(16) uint32_t smem[5120 + 2304];
    uint32_t* XsBase = smem;            // +b*2560, half2 [128][20]
    uint32_t* WsBase = smem + 5120;     // +b*1152, half2 [16][72]
    uint32_t (*H2)[36]  = (uint32_t(*)[36])smem;
    uint32_t (*W2p)[72] = (uint32_t(*)[72])(smem + 5120);

    const int t    = threadIdx.x;
    const int lane = t & 31;
    const int wid  = t >> 5;
    const int wm   = wid & 3;
    const int wn   = wid >> 2;
    const int g    = lane >> 2;
    const int tq   = lane & 3;
    const int rb   = blockIdx.x * BM;

    const int xrow[4] = { (t) >> 3, (t + 256) >> 3, (t + 512) >> 3, (t + 768) >> 3 };
    const int xc4     = (t & 7) * 4;
    const int wkp     = t >> 4;          // k-pair row 0..15
    const int wc4     = (t & 15) * 4;

    float4 xr[4], wrA, wrB;

    auto load_tiles = [&](int cc) {
        const int kb = cc * KCH;
#pragma unroll
        for (int l = 0; l < 4; l++) {
            int grow = rb + xrow[l];
            xr[l] = (grow < N_NODES)
                  ? __ldcs((const float4*)(X + (size_t)grow * F_IN + kb + xc4))
                  : make_float4(0.f, 0.f, 0.f, 0.f);
        }
        wrA = *(const float4*)(W1 + (size_t)(kb + 2 * wkp    ) * HID + wc4);
        wrB = *(const float4*)(W1 + (size_t)(kb + 2 * wkp + 1) * HID + wc4);
    };
    auto store_tiles = [&](int b) {
        uint32_t* Xs = XsBase + b * 2560;
        uint32_t* Wp = WsBase + b * 1152;
#pragma unroll
        for (int l = 0; l < 4; l++) {
            __half2 h0 = __floats2half2_rn(xr[l].x, xr[l].y);
            __half2 h1 = __floats2half2_rn(xr[l].z, xr[l].w);
            uint2 u; u.x = *(uint32_t*)&h0; u.y = *(uint32_t*)&h1;
            *(uint2*)(Xs + xrow[l] * 20 + (xc4 >> 1)) = u;
        }
        __half2 p0 = __floats2half2_rn(wrA.x, wrB.x);
        __half2 p1 = __floats2half2_rn(wrA.y, wrB.y);
        __half2 p2 = __floats2half2_rn(wrA.z, wrB.z);
        __half2 p3 = __floats2half2_rn(wrA.w, wrB.w);
        uint4 u; u.x = *(uint32_t*)&p0; u.y = *(uint32_t*)&p1;
        u.z = *(uint32_t*)&p2; u.w = *(uint32_t*)&p3;
        *(uint4*)(Wp + wkp * 72 + wc4) = u;
    };

    float c1[2][4][4];
#pragma unroll
    for (int m = 0; m < 2; m++)
#pragma unroll
        for (int n = 0; n < 4; n++)
#pragma unroll
            for (int i = 0; i < 4; i++) c1[m][n][i] = 0.0f;

    load_tiles(0);
    store_tiles(0);
    __syncthreads();

#pragma unroll 1
    for (int cc = 0; cc < NCHUNK; cc++) {
        if (cc + 1 < NCHUNK) load_tiles(cc + 1);

        const uint32_t* Xs = XsBase + (cc & 1) * 2560;
        const uint32_t* Wp = WsBase + (cc & 1) * 1152;
#pragma unroll
        for (int ka = 0; ka < 2; ka++) {
            const int kp = ka * 8;
            uint32_t a[2][4];
#pragma unroll
            for (int m = 0; m < 2; m++) {
                int row = wm * 32 + m * 16;
                a[m][0] = Xs[(row + g    ) * 20 + kp + tq];
                a[m][1] = Xs[(row + g + 8) * 20 + kp + tq];
                a[m][2] = Xs[(row + g    ) * 20 + kp + tq + 4];
                a[m][3] = Xs[(row + g + 8) * 20 + kp + tq + 4];
            }
            uint32_t b[4][2];
#pragma unroll
            for (int n = 0; n < 4; n++) {
                int col = wn * 32 + n * 8 + g;
                b[n][0] = Wp[(kp + tq    ) * 72 + col];
                b[n][1] = Wp[(kp + tq + 4) * 72 + col];
            }
#pragma unroll
            for (int m = 0; m < 2; m++)
#pragma unroll
                for (int n = 0; n < 4; n++)
                    mma_f16(c1[m][n], a[m], b[n]);
        }

        if (cc + 1 < NCHUNK) store_tiles((cc + 1) & 1);
        __syncthreads();
    }

    // bias + relu -> fp16 pairs into H2
#pragma unroll
    for (int n = 0; n < 4; n++) {
        float2 bb = *(const float2*)(b1 + wn * 32 + n * 8 + 2 * tq);
        int colp = wn * 16 + n * 4 + tq;
#pragma unroll
        for (int m = 0; m < 2; m++) {
            int row = wm * 32 + m * 16 + g;
            float h0 = fmaxf(c1[m][n][0] + bb.x, 0.f);
            float h1 = fmaxf(c1[m][n][1] + bb.y, 0.f);
            float h2 = fmaxf(c1[m][n][2] + bb.x, 0.f);
            float h3 = fmaxf(c1[m][n][3] + bb.y, 0.f);
            __half2 p0 = __floats2half2_rn(h0, h1);
            __half2 p1 = __floats2half2_rn(h2, h3);
            H2[row    ][colp] = *(uint32_t*)&p0;
            H2[row + 8][colp] = *(uint32_t*)&p1;
        }
    }
    // W2 -> fp16 k-pair layout
#pragma unroll
    for (int l = 0; l < 8; l++) {
        int idx = t + l * 256;
        int kp  = idx >> 6;
        int n   = idx & 63;
        float w0 = W2[(size_t)(2 * kp    ) * NCLS + n];
        float w1 = W2[(size_t)(2 * kp + 1) * NCLS + n];
        __half2 p = __floats2half2_rn(w0, w1);
        W2p[kp][n] = *(uint32_t*)&p;
    }
    __syncthreads();

    float c2[2][4][4];
#pragma unroll
    for (int m = 0; m < 2; m++)
#pragma unroll
        for (int n = 0; n < 4; n++)
#pragma unroll
            for (int i = 0; i < 4; i++) c2[m][n][i] = 0.0f;

#pragma unroll
    for (int ka = 0; ka < 4; ka++) {
        const int kp = ka * 8;
        uint32_t a[2][4];
#pragma unroll
        for (int m = 0; m < 2; m++) {
            int row = wm * 32 + m * 16;
            a[m][0] = H2[row + g    ][kp + tq];
            a[m][1] = H2[row + g + 8][kp + tq];
            a[m][2] = H2[row + g    ][kp + tq + 4];
            a[m][3] = H2[row + g + 8][kp + tq + 4];
        }
        uint32_t b[4][2];
#pragma unroll
        for (int n = 0; n < 4; n++) {
            int col = wn * 32 + n * 8 + g;
            b[n][0] = W2p[kp + tq    ][col];
            b[n][1] = W2p[kp + tq + 4][col];
        }
#pragma unroll
        for (int m = 0; m < 2; m++)
#pragma unroll
            for (int n = 0; n < 4; n++)
                mma_f16(c2[m][n], a[m], b[n]);
    }

    // + b2, store logits as fp16
    __half2* lg2 = (__half2*)g_logits_h;
#pragma unroll
    for (int n = 0; n < 4; n++) {
        float2 bb = *(const float2*)(b2 + wn * 32 + n * 8 + 2 * tq);
        int colp = wn * 16 + n * 4 + tq;
#pragma unroll
        for (int m = 0; m < 2; m++) {
            int row = rb + wm * 32 + m * 16 + g;
            if (row < N_NODES)
                lg2[(size_t)row * 32 + colp] =
                    __floats2half2_rn(c2[m][n][0] + bb.x, c2[m][n][1] + bb.y);
            if (row + 8 < N_NODES)
                lg2[(size_t)(row + 8) * 32 + colp] =
                    __floats2half2_rn(c2[m][n][2] + bb.x, c2[m][n][3] + bb.y);
        }
    }
}

// ---------------------------------------------------------------------------
// CSR build: histogram -> scan -> scatter (4 edges/thread, vectorized)
// ---------------------------------------------------------------------------
__global__ __launch_bounds__(256) void hist_k(const int* __restrict__ rows, int E)
{
    int base = (blockIdx.x * 256 + threadIdx.x) * 4;
    if (base + 3 < E) {
        int4 r = *(const int4*)(rows + base);
        atomicAdd(&g_cnt[r.x], 1);
        atomicAdd(&g_cnt[r.y], 1);
        atomicAdd(&g_cnt[r.z], 1);
        atomicAdd(&g_cnt[r.w], 1);
    } else {
        for (int e = base; e < E; e++) atomicAdd(&g_cnt[rows[e]], 1);
    }
}

__global__ __launch_bounds__(256) void scan1_k(int n)
{
    __shared__ int wsum[8];
    const int t = threadIdx.x, b = blockIdx.x;
    const int base = b * 1024 + t * 4;
    int v0 = 0, v1 = 0, v2 = 0, v3 = 0;
    if (base + 0 < n) v0 = g_cnt[base + 0];
    if (base + 1 < n) v1 = g_cnt[base + 1];
    if (base + 2 < n) v2 = g_cnt[base + 2];
    if (base + 3 < n) v3 = g_cnt[base + 3];
    const int tsum = v0 + v1 + v2 + v3;
    const int lane = t & 31, w = t >> 5;
    int inc = tsum;
#pragma unroll
    for (int d = 1; d < 32; d <<= 1) {
        int y = __shfl_up_sync(0xffffffffu, inc, d);
        if (lane >= d) inc += y;
    }
    if (lane == 31) wsum[w] = inc;
    __syncthreads();
    if (t < 8) {
        int x = wsum[t];
#pragma unroll
        for (int d = 1; d < 8; d <<= 1) {
            int y = __shfl_up_sync(0xffu, x, d);
            if (t >= d) x += y;
        }
        wsum[t] = x;
    }
    __syncthreads();
    const int wprefix = (w == 0) ? 0 : wsum[w - 1];
    const int texcl = wprefix + inc - tsum;
    if (base + 0 < n) g_off[base + 0] = texcl;
    if (base + 1 < n) g_off[base + 1] = texcl + v0;
    if (base + 2 < n) g_off[base + 2] = texcl + v0 + v1;
    if (base + 3 < n) g_off[base + 3] = texcl + v0 + v1 + v2;
    if (t == 255) g_bsum[b] = wsum[7];
}

__global__ __launch_bounds__(128) void scan2_k(int nb)
{
    __shared__ int wsum[4];
    const int t = threadIdx.x;
    int x0 = (t < nb) ? g_bsum[t] : 0;
    const int lane = t & 31, w = t >> 5;
    int x = x0;
#pragma unroll
    for (int d = 1; d < 32; d <<= 1) {
        int y = __shfl_up_sync(0xffffffffu, x, d);
        if (lane >= d) x += y;
    }
    if (lane == 31) wsum[w] = x;
    __syncthreads();
    if (t < 4) {
        int y = wsum[t];
#pragma unroll
        for (int d = 1; d < 4; d <<= 1) {
            int z = __shfl_up_sync(0xfu, y, d);
            if (t >= d) y += z;
        }
        wsum[t] = y;
    }
    __syncthreads();
    const int wprefix = (w == 0) ? 0 : wsum[w - 1];
    if (t < nb) g_bsum[t] = wprefix + x - x0;   // exclusive
}

__global__ __launch_bounds__(256) void scan3_k(int n)
{
    int i = blockIdx.x * 256 + threadIdx.x;
    if (i < n) {
        int o = g_off[i] + g_bsum[i >> 10];
        g_off[i] = o;
        g_run[i] = o;
    }
}

__device__ __forceinline__ void epack_store(int p, int col, float val) {
    int2 e = make_int2(col, __float_as_int(val));
    __stcs(&g_epack[p], e);   // evict-first: don't displace logits in L2
}

__global__ __launch_bounds__(256) void build_k(
    const int* __restrict__ rows, const int* __restrict__ cols,
    const float* __restrict__ vals, int E)
{
    int base = (blockIdx.x * 256 + threadIdx.x) * 4;
    if (base + 3 < E) {
        int4   r = *(const int4*)(rows + base);
        int4   c = *(const int4*)(cols + base);
        float4 v = *(const float4*)(vals + base);
        epack_store(atomicAdd(&g_run[r.x], 1), c.x, v.x);
        epack_store(atomicAdd(&g_run[r.y], 1), c.y, v.y);
        epack_store(atomicAdd(&g_run[r.z], 1), c.z, v.z);
        epack_store(atomicAdd(&g_run[r.w], 1), c.w, v.w);
    } else {
        for (int e = base; e < E; e++)
            epack_store(atomicAdd(&g_run[rows[e]], 1), cols[e], vals[e]);
    }
}

// ---------------------------------------------------------------------------
// Reduce: one warp per node, four 8-lane groups, each unrolled x2 ->
// EIGHT independent gather chains in flight per warp. Lane gathers uint4
// (16B = 8 fp16 cols); 8 lanes cover the 128B row. Next iteration's epack
// pair prefetched before the gathers issue. Out-of-range slots use
// {col=0, val=0}: gathers L2-hot row 0, contributes 0. Atomic-free.
// ---------------------------------------------------------------------------
__global__ __launch_bounds__(256) void reduce_k(float* __restrict__ out)
{
    const int wid  = threadIdx.x >> 5;
    const int lane = threadIdx.x & 31;
    const int n    = blockIdx.x * 8 + wid;
    if (n >= N_NODES) return;

    const int s   = g_off[n];
    const int m   = g_cnt[n];
    const int end = s + m;
    const int grp = lane >> 3;    // 0..3: edge-stream group
    const int j   = lane & 7;     // uint4 index within 64-col row

    const uint4* __restrict__ lg4 = (const uint4*)g_logits_h;  // row = 8 uint4

    float aA0 = 0.f, aA1 = 0.f, aA2 = 0.f, aA3 = 0.f;
    float aA4 = 0.f, aA5 = 0.f, aA6 = 0.f, aA7 = 0.f;
    float aB0 = 0.f, aB1 = 0.f, aB2 = 0.f, aB3 = 0.f;
    float aB4 = 0.f, aB5 = 0.f, aB6 = 0.f, aB7 = 0.f;

    int p = s + grp;
    int2 e0 = (p     < end) ? __ldcs(&g_epack[p])     : make_int2(0, 0);
    int2 e1 = (p + 4 < end) ? __ldcs(&g_epack[p + 4]) : make_int2(0, 0);

#pragma unroll 1
    while (p < end) {
        int2 f0 = (p + 8  < end) ? __ldcs(&g_epack[p + 8])  : make_int2(0, 0);
        int2 f1 = (p + 12 < end) ? __ldcs(&g_epack[p + 12]) : make_int2(0, 0);

        uint4 q0 = lg4[(size_t)e0.x * 8 + j];
        uint4 q1 = lg4[(size_t)e1.x * 8 + j];
        float v0 = __int_as_float(e0.y);
        float v1 = __int_as_float(e1.y);

        float2 g0 = __half22float2(*(const __half2*)&q0.x);
        float2 g1 = __half22float2(*(const __half2*)&q0.y);
        float2 g2 = __half22float2(*(const __half2*)&q0.z);
        float2 g3 = __half22float2(*(const __half2*)&q0.w);
        aA0 = fmaf(v0, g0.x, aA0); aA1 = fmaf(v0, g0.y, aA1);
        aA2 = fmaf(v0, g1.x, aA2); aA3 = fmaf(v0, g1.y, aA3);
        aA4 = fmaf(v0, g2.x, aA4); aA5 = fmaf(v0, g2.y, aA5);
        aA6 = fmaf(v0, g3.x, aA6); aA7 = fmaf(v0, g3.y, aA7);

        float2 h0 = __half22float2(*(const __half2*)&q1.x);
        float2 h1 = __half22float2(*(const __half2*)&q1.y);
        float2 h2 = __half22float2(*(const __half2*)&q1.z);
        float2 h3 = __half22float2(*(const __half2*)&q1.w);
        aB0 = fmaf(v1, h0.x, aB0); aB1 = fmaf(v1, h0.y, aB1);
        aB2 = fmaf(v1, h1.x, aB2); aB3 = fmaf(v1, h1.y, aB3);
        aB4 = fmaf(v1, h2.x, aB4); aB5 = fmaf(v1, h2.y, aB5);
        aB6 = fmaf(v1, h3.x, aB6); aB7 = fmaf(v1, h3.y, aB7);

        e0 = f0; e1 = f1; p += 8;
    }

    float a0 = aA0 + aB0, a1 = aA1 + aB1, a2 = aA2 + aB2, a3 = aA3 + aB3;
    float a4 = aA4 + aB4, a5 = aA5 + aB5, a6 = aA6 + aB6, a7 = aA7 + aB7;

    // combine the four groups (column mapping identical across groups)
#pragma unroll
    for (int d = 8; d <= 16; d <<= 1) {
        a0 += __shfl_xor_sync(0xffffffffu, a0, d);
        a1 += __shfl_xor_sync(0xffffffffu, a1, d);
        a2 += __shfl_xor_sync(0xffffffffu, a2, d);
        a3 += __shfl_xor_sync(0xffffffffu, a3, d);
        a4 += __shfl_xor_sync(0xffffffffu, a4, d);
        a5 += __shfl_xor_sync(0xffffffffu, a5, d);
        a6 += __shfl_xor_sync(0xffffffffu, a6, d);
        a7 += __shfl_xor_sync(0xffffffffu, a7, d);
    }

    if (grp == 0) {
        float4 o0; o0.x = a0; o0.y = a1; o0.z = a2; o0.w = a3;
        float4 o1; o1.x = a4; o1.y = a5; o1.z = a6; o1.w = a7;
        __stcs((float4*)(out + (size_t)n * NCLS + j * 8), o0);
        __stcs((float4*)(out + (size_t)n * NCLS + j * 8 + 4), o1);
    }
}

// ---------------------------------------------------------------------------
// Launch: fork the CSR-build chain onto a side stream so it overlaps the MLP.
// ---------------------------------------------------------------------------
extern "C" void kernel_launch(void* const* d_in, const int* in_sizes, int n_in,
                              void* d_out, int out_size)
{
    const float* X    = (const float*)d_in[0];
    const int*   erow = (const int*)  d_in[1];
    const int*   ecol = (const int*)  d_in[2];
    const float* ev   = (const float*)d_in[3];
    const float* W1   = (const float*)d_in[4];
    const float* b1   = (const float*)d_in[5];
    const float* W2   = (const float*)d_in[6];
    const float* b2   = (const float*)d_in[7];
    float* out = (float*)d_out;
    const int E = in_sizes[1];

    cudaStream_t s2;
    cudaEvent_t evFork, evJoin;
    cudaStreamCreateWithFlags(&s2, cudaStreamNonBlocking);
    cudaEventCreateWithFlags(&evFork, cudaEventDisableTiming);
    cudaEventCreateWithFlags(&evJoin, cudaEventDisableTiming);

    cudaEventRecord(evFork, 0);
    cudaStreamWaitEvent(s2, evFork, 0);

    // Branch A (s2): CSR build chain.
    void* cnt_ptr = nullptr;
    cudaGetSymbolAddress(&cnt_ptr, g_cnt);
    cudaMemsetAsync(cnt_ptr, 0, N_NODES * sizeof(int), s2);
    const int eb4 = (E / 4 + 255) / 256;
    hist_k <<<eb4, 256, 0, s2>>>(erow, E);
    scan1_k<<<SCAN_NB, 256, 0, s2>>>(N_NODES);
    scan2_k<<<1, 128, 0, s2>>>(SCAN_NB);
    scan3_k<<<(N_NODES + 255) / 256, 256, 0, s2>>>(N_NODES);
    build_k<<<eb4, 256, 0, s2>>>(erow, ecol, ev, E);
    cudaEventRecord(evJoin, s2);

    // Branch B (origin stream): MLP.
    mlp_mma<<<(N_NODES + BM - 1) / BM, 256>>>(X, W1, b1, W2, b2);

    // Join, then reduce.
    cudaStreamWaitEvent(0, evJoin, 0);
    reduce_k<<<(N_NODES + 7) / 8, 256>>>(out);
}